// round 1
// baseline (speedup 1.0000x reference)
#include <cuda_runtime.h>

#define NN 50000
#define EE 600000
#define ET (EE + NN)
#define KDIM 256
#define SCAN_B 1024
#define NBLK ((NN + SCAN_B - 1) / SCAN_B)

// ---------------- scratch (device globals; no allocation allowed) ----------------
__device__ float g_h[(size_t)NN * 256];     // post-GEMM features of current layer
__device__ float g_feat[(size_t)NN * 256];  // layer output / next layer input
__device__ float g_as[NN * 4];
__device__ float g_ad[NN * 4];
__device__ int   g_cnt[NN];
__device__ int   g_incl[NBLK * SCAN_B];
__device__ int   g_bsum[NBLK];
__device__ int   g_rowptr[NN + 1];
__device__ int   g_fill[NN];
__device__ int   g_col[ET];

// ---------------- CSR build (dst-sorted adjacency, self-loops included) ----------
__global__ void k_zero_cnt() {
    int i = blockIdx.x * blockDim.x + threadIdx.x;
    if (i < NN) g_cnt[i] = 0;
}

__global__ void k_count(const int* __restrict__ ei) {
    int e = blockIdx.x * blockDim.x + threadIdx.x;
    if (e >= ET) return;
    int d = (e < EE) ? ei[EE + e] : (e - EE);  // self-loop for e >= EE
    atomicAdd(&g_cnt[d], 1);
}

__global__ void k_scan1() {
    __shared__ int sh[SCAN_B];
    int tid = threadIdx.x;
    int i = blockIdx.x * SCAN_B + tid;
    int v = (i < NN) ? g_cnt[i] : 0;
    sh[tid] = v;
    __syncthreads();
    for (int off = 1; off < SCAN_B; off <<= 1) {
        int t = (tid >= off) ? sh[tid - off] : 0;
        __syncthreads();
        sh[tid] += t;
        __syncthreads();
    }
    g_incl[i] = sh[tid];
    if (tid == SCAN_B - 1) g_bsum[blockIdx.x] = sh[tid];
}

__global__ void k_scan2() {
    if (threadIdx.x == 0) {
        int s = 0;
        for (int i = 0; i < NBLK; ++i) { int t = g_bsum[i]; g_bsum[i] = s; s += t; }
    }
}

__global__ void k_scan3() {
    int i = blockIdx.x * blockDim.x + threadIdx.x;
    if (i < NN) {
        int v = (i < NN) ? g_cnt[i] : 0;
        int ex = g_incl[i] - v + g_bsum[i >> 10];
        g_rowptr[i] = ex;
        g_fill[i] = ex;
    }
    if (i == 0) g_rowptr[NN] = ET;
}

__global__ void k_fill(const int* __restrict__ ei) {
    int e = blockIdx.x * blockDim.x + threadIdx.x;
    if (e >= ET) return;
    int s, d;
    if (e < EE) { s = ei[e]; d = ei[EE + e]; }
    else        { s = e - EE; d = s; }
    int pos = atomicAdd(&g_fill[d], 1);
    g_col[pos] = s;
}

// ---------------- GEMM: C[N, NO] = A[N, 256] @ W[256, NO]  (no bias) ------------
template <int NO>
__global__ __launch_bounds__(256) void k_gemm(const float* __restrict__ A,
                                              const float* __restrict__ W,
                                              float* __restrict__ C) {
    __shared__ float As[16][65];
    __shared__ float Bs[16][64];
    const int tid = threadIdx.x;
    const int tx = tid & 15, ty = tid >> 4;
    const int bm = blockIdx.y * 64, bn = blockIdx.x * 64;
    const int ar = tid >> 2, kq = (tid & 3) * 4;   // A tile loader coords
    const int br = tid >> 4, bc = (tid & 15) * 4;  // B tile loader coords
    float acc[4][4] = {};

    for (int bk = 0; bk < KDIM; bk += 16) {
        float4 av = make_float4(0.f, 0.f, 0.f, 0.f);
        int gm = bm + ar;
        if (gm < NN) av = *(const float4*)(A + (size_t)gm * KDIM + bk + kq);
        As[kq + 0][ar] = av.x; As[kq + 1][ar] = av.y;
        As[kq + 2][ar] = av.z; As[kq + 3][ar] = av.w;
        float4 bv = *(const float4*)(W + (size_t)(bk + br) * NO + bn + bc);
        *(float4*)&Bs[br][bc] = bv;
        __syncthreads();
#pragma unroll
        for (int k = 0; k < 16; ++k) {
            float a0 = As[k][ty * 4 + 0], a1 = As[k][ty * 4 + 1];
            float a2 = As[k][ty * 4 + 2], a3 = As[k][ty * 4 + 3];
            float4 b4 = *(const float4*)&Bs[k][tx * 4];
            acc[0][0] += a0 * b4.x; acc[0][1] += a0 * b4.y; acc[0][2] += a0 * b4.z; acc[0][3] += a0 * b4.w;
            acc[1][0] += a1 * b4.x; acc[1][1] += a1 * b4.y; acc[1][2] += a1 * b4.z; acc[1][3] += a1 * b4.w;
            acc[2][0] += a2 * b4.x; acc[2][1] += a2 * b4.y; acc[2][2] += a2 * b4.z; acc[2][3] += a2 * b4.w;
            acc[3][0] += a3 * b4.x; acc[3][1] += a3 * b4.y; acc[3][2] += a3 * b4.z; acc[3][3] += a3 * b4.w;
        }
        __syncthreads();
    }
#pragma unroll
    for (int i = 0; i < 4; ++i) {
        int gm = bm + ty * 4 + i;
        if (gm < NN) {
#pragma unroll
            for (int j = 0; j < 4; ++j)
                C[(size_t)gm * NO + bn + tx * 4 + j] = acc[i][j];
        }
    }
}

// ---------------- per-node attention logits alpha_s, alpha_d ---------------------
template <int HEADS>
__global__ __launch_bounds__(256) void k_alpha(const float* __restrict__ h,
                                               const float* __restrict__ a_s,
                                               const float* __restrict__ a_d,
                                               float* __restrict__ as_out,
                                               float* __restrict__ ad_out) {
    int warp = (blockIdx.x * blockDim.x + threadIdx.x) >> 5;
    int lane = threadIdx.x & 31;
    if (warp >= NN) return;
    const float* hr = h + (size_t)warp * HEADS * 64;
#pragma unroll
    for (int hh = 0; hh < HEADS; ++hh) {
        float v0 = hr[hh * 64 + lane], v1 = hr[hh * 64 + lane + 32];
        float ps = v0 * a_s[hh * 64 + lane] + v1 * a_s[hh * 64 + lane + 32];
        float pd = v0 * a_d[hh * 64 + lane] + v1 * a_d[hh * 64 + lane + 32];
#pragma unroll
        for (int o = 16; o; o >>= 1) {
            ps += __shfl_xor_sync(0xffffffffu, ps, o);
            pd += __shfl_xor_sync(0xffffffffu, pd, o);
        }
        if (lane == 0) { as_out[warp * HEADS + hh] = ps; ad_out[warp * HEADS + hh] = pd; }
    }
}

// ---------------- GAT conv: warp per dst node; softmax + gather-aggregate -------
template <int HEADS, bool RELU>
__global__ __launch_bounds__(256) void k_conv(const float* __restrict__ h,
                                              const float* __restrict__ as_,
                                              const float* __restrict__ ad_,
                                              const float* __restrict__ bias,
                                              float* __restrict__ out) {
    const int TC = HEADS * 64;
    const int NPL = TC / 32;  // channels per lane: 8 (H=4) or 2 (H=1)
    int warp = (blockIdx.x * blockDim.x + threadIdx.x) >> 5;
    int lane = threadIdx.x & 31;
    if (warp >= NN) return;
    int beg = g_rowptr[warp], end = g_rowptr[warp + 1];

    float adh[HEADS];
#pragma unroll
    for (int hh = 0; hh < HEADS; ++hh) adh[hh] = ad_[warp * HEADS + hh];

    // pass 1: per-head max over incoming edges
    float mx[HEADS];
#pragma unroll
    for (int hh = 0; hh < HEADS; ++hh) mx[hh] = -1e30f;
    for (int i = beg + lane; i < end; i += 32) {
        int s = g_col[i];
#pragma unroll
        for (int hh = 0; hh < HEADS; ++hh) {
            float e = as_[s * HEADS + hh] + adh[hh];
            e = e > 0.f ? e : 0.2f * e;
            mx[hh] = fmaxf(mx[hh], e);
        }
    }
#pragma unroll
    for (int hh = 0; hh < HEADS; ++hh)
#pragma unroll
        for (int o = 16; o; o >>= 1)
            mx[hh] = fmaxf(mx[hh], __shfl_xor_sync(0xffffffffu, mx[hh], o));

    // pass 2: per-head exp-sum
    float sm[HEADS] = {};
    for (int i = beg + lane; i < end; i += 32) {
        int s = g_col[i];
#pragma unroll
        for (int hh = 0; hh < HEADS; ++hh) {
            float e = as_[s * HEADS + hh] + adh[hh];
            e = e > 0.f ? e : 0.2f * e;
            sm[hh] += __expf(e - mx[hh]);
        }
    }
#pragma unroll
    for (int hh = 0; hh < HEADS; ++hh)
#pragma unroll
        for (int o = 16; o; o >>= 1)
            sm[hh] += __shfl_xor_sync(0xffffffffu, sm[hh], o);

    // pass 3: weighted gather-aggregate; lane owns NPL contiguous channels
    const int myhead = (lane * NPL) / 64;
    float mm = mx[myhead], adm = adh[myhead], inv = 1.f / sm[myhead];
    float acc[NPL] = {};
    for (int i = beg; i < end; ++i) {
        int s = g_col[i];
        float e = as_[s * HEADS + myhead] + adm;
        e = e > 0.f ? e : 0.2f * e;
        float w = __expf(e - mm) * inv;
        const float* hp = h + (size_t)s * TC + lane * NPL;
        if constexpr (NPL == 8) {
            float4 x0 = *(const float4*)hp;
            float4 x1 = *(const float4*)(hp + 4);
            acc[0] += w * x0.x; acc[1] += w * x0.y; acc[2] += w * x0.z; acc[3] += w * x0.w;
            acc[4] += w * x1.x; acc[5] += w * x1.y; acc[6] += w * x1.z; acc[7] += w * x1.w;
        } else {
            float2 x0 = *(const float2*)hp;
            acc[0] += w * x0.x; acc[1] += w * x0.y;
        }
    }
    float dinv = 1.f / (float)(end - beg);
#pragma unroll
    for (int j = 0; j < NPL; ++j) {
        float v = acc[j] * dinv + bias[lane * NPL + j];
        if (RELU) v = fmaxf(v, 0.f);
        out[(size_t)warp * TC + lane * NPL + j] = v;
    }
}

// ---------------- launch --------------------------------------------------------
extern "C" void kernel_launch(void* const* d_in, const int* in_sizes, int n_in,
                              void* d_out, int out_size) {
    const float* x   = (const float*)d_in[0];
    const int*   ei  = (const int*)d_in[1];
    const float* W0  = (const float*)d_in[2];
    const float* a0s = (const float*)d_in[3];
    const float* a0d = (const float*)d_in[4];
    const float* b0  = (const float*)d_in[5];
    const float* W1  = (const float*)d_in[6];
    const float* a1s = (const float*)d_in[7];
    const float* a1d = (const float*)d_in[8];
    const float* b1  = (const float*)d_in[9];
    const float* W2  = (const float*)d_in[10];
    const float* a2s = (const float*)d_in[11];
    const float* a2d = (const float*)d_in[12];
    const float* b2  = (const float*)d_in[13];
    float* out = (float*)d_out;

    void* p;
    cudaGetSymbolAddress(&p, g_h);    float* hbuf = (float*)p;
    cudaGetSymbolAddress(&p, g_feat); float* feat = (float*)p;
    cudaGetSymbolAddress(&p, g_as);   float* asb  = (float*)p;
    cudaGetSymbolAddress(&p, g_ad);   float* adb  = (float*)p;

    const int WPB = 8;                      // warps per block for node-parallel kernels
    const int NODE_BLKS = (NN + WPB - 1) / WPB;
    dim3 gemm_grid256(4, (NN + 63) / 64);
    dim3 gemm_grid64(1, (NN + 63) / 64);

    // CSR build
    k_zero_cnt<<<(NN + 255) / 256, 256>>>();
    k_count<<<(ET + 255) / 256, 256>>>(ei);
    k_scan1<<<NBLK, SCAN_B>>>();
    k_scan2<<<1, 32>>>();
    k_scan3<<<(NN + 255) / 256, 256>>>();
    k_fill<<<(ET + 255) / 256, 256>>>(ei);

    // layer 0: x -> feat
    k_gemm<256><<<gemm_grid256, 256>>>(x, W0, hbuf);
    k_alpha<4><<<NODE_BLKS, 256>>>(hbuf, a0s, a0d, asb, adb);
    k_conv<4, true><<<NODE_BLKS, 256>>>(hbuf, asb, adb, b0, feat);

    // layer 1: feat -> feat
    k_gemm<256><<<gemm_grid256, 256>>>(feat, W1, hbuf);
    k_alpha<4><<<NODE_BLKS, 256>>>(hbuf, a1s, a1d, asb, adb);
    k_conv<4, true><<<NODE_BLKS, 256>>>(hbuf, asb, adb, b1, feat);

    // layer 2: feat -> out (heads=1)
    k_gemm<64><<<gemm_grid64, 256>>>(feat, W2, hbuf);
    k_alpha<1><<<NODE_BLKS, 256>>>(hbuf, a2s, a2d, asb, adb);
    k_conv<1, false><<<NODE_BLKS, 256>>>(hbuf, asb, adb, b2, out);
}

// round 3
// speedup vs baseline: 1.6815x; 1.6815x over previous
#include <cuda_runtime.h>
#include <cuda_bf16.h>
#include <cstdint>

#define NN 50000
#define EE 600000
#define ET (EE + NN)
#define KDIM 256
#define SCAN_B 1024
#define NBLK ((NN + SCAN_B - 1) / SCAN_B)

// ---------------- scratch (device globals; no allocation allowed) ----------------
__device__ float g_h[(size_t)NN * 256];           // post-GEMM features (fp32)
__device__ __nv_bfloat16 g_ahi[(size_t)NN * 256]; // GEMM A operand, hi part
__device__ __nv_bfloat16 g_alo[(size_t)NN * 256]; // GEMM A operand, lo part
__device__ __nv_bfloat16 g_w0hi[256 * 256], g_w0lo[256 * 256];  // Wt [NO,K] bf16
__device__ __nv_bfloat16 g_w1hi[256 * 256], g_w1lo[256 * 256];
__device__ __nv_bfloat16 g_w2hi[64 * 256],  g_w2lo[64 * 256];
__device__ float g_as[NN * 4];
__device__ float g_ad[NN * 4];
__device__ int   g_cnt[NN];
__device__ int   g_incl[NBLK * SCAN_B];
__device__ int   g_bsum[NBLK];
__device__ int   g_rowptr[NN + 1];
__device__ int   g_fill[NN];
__device__ int   g_col[ET];

// ---------------- PTX helpers ----------------------------------------------------
__device__ __forceinline__ uint32_t smem_u32(const void* p) {
    uint32_t a;
    asm("{ .reg .u64 t; cvta.to.shared.u64 t, %1; cvt.u32.u64 %0, t; }" : "=r"(a) : "l"(p));
    return a;
}
__device__ __forceinline__ void cp_async16(uint32_t dst, const void* src) {
    asm volatile("cp.async.cg.shared.global [%0], [%1], 16;"
                 :: "r"(dst), "l"(__cvta_generic_to_global(src)) : "memory");
}
__device__ __forceinline__ void ldsm_x4(uint32_t& r0, uint32_t& r1, uint32_t& r2,
                                        uint32_t& r3, uint32_t addr) {
    asm volatile("ldmatrix.sync.aligned.m8n8.x4.shared.b16 {%0,%1,%2,%3}, [%4];"
                 : "=r"(r0), "=r"(r1), "=r"(r2), "=r"(r3) : "r"(addr));
}
__device__ __forceinline__ void mma16816(float* c, const uint32_t* a, const uint32_t* b) {
    asm volatile("mma.sync.aligned.m16n8k16.row.col.f32.bf16.bf16.f32 "
                 "{%0,%1,%2,%3}, {%4,%5,%6,%7}, {%8,%9}, {%0,%1,%2,%3};"
                 : "+f"(c[0]), "+f"(c[1]), "+f"(c[2]), "+f"(c[3])
                 : "r"(a[0]), "r"(a[1]), "r"(a[2]), "r"(a[3]), "r"(b[0]), "r"(b[1]));
}
#define SW128(o) ((o) ^ (((o) >> 3) & 0x70))

// ---------------- split conversions ----------------------------------------------
__global__ void k_split_x(const float* __restrict__ x) {
    int i = blockIdx.x * blockDim.x + threadIdx.x;  // one float4
    if (i >= NN * 64) return;
    float4 v = ((const float4*)x)[i];
    __nv_bfloat16 h0 = __float2bfloat16(v.x), h1 = __float2bfloat16(v.y);
    __nv_bfloat16 h2 = __float2bfloat16(v.z), h3 = __float2bfloat16(v.w);
    __nv_bfloat16 l0 = __float2bfloat16(v.x - __bfloat162float(h0));
    __nv_bfloat16 l1 = __float2bfloat16(v.y - __bfloat162float(h1));
    __nv_bfloat16 l2 = __float2bfloat16(v.z - __bfloat162float(h2));
    __nv_bfloat16 l3 = __float2bfloat16(v.w - __bfloat162float(h3));
    ((__nv_bfloat162*)g_ahi)[2 * i]     = __nv_bfloat162(h0, h1);
    ((__nv_bfloat162*)g_ahi)[2 * i + 1] = __nv_bfloat162(h2, h3);
    ((__nv_bfloat162*)g_alo)[2 * i]     = __nv_bfloat162(l0, l1);
    ((__nv_bfloat162*)g_alo)[2 * i + 1] = __nv_bfloat162(l2, l3);
}

template <int NO>
__global__ void k_split_wt(const float* __restrict__ W, __nv_bfloat16* __restrict__ hi,
                           __nv_bfloat16* __restrict__ lo) {
    int i = blockIdx.x * blockDim.x + threadIdx.x;
    if (i >= 256 * NO) return;
    int k = i / NO, n = i % NO;
    float v = W[i];
    __nv_bfloat16 h = __float2bfloat16(v);
    hi[n * 256 + k] = h;
    lo[n * 256 + k] = __float2bfloat16(v - __bfloat162float(h));
}

// ---------------- mma.sync GEMM: C[NN,NO] = A[NN,256] @ Wt^T, hi/lo split --------
// Virtual K = 768: chunks 0-3 Ahi*Bhi, 4-7 Alo*Bhi, 8-11 Ahi*Blo (lo*lo dropped).
template <int NO>
__global__ __launch_bounds__(256) void k_gemm_mma(const __nv_bfloat16* __restrict__ Ahi,
                                                  const __nv_bfloat16* __restrict__ Alo,
                                                  const __nv_bfloat16* __restrict__ Bhi,
                                                  const __nv_bfloat16* __restrict__ Blo,
                                                  float* __restrict__ C) {
    constexpr int BM = 128, BN = (NO == 256) ? 128 : 64;
    constexpr int WN = BN / 2;        // warp tile: 32 x WN  (warp grid 4x2)
    constexpr int NG = WN / 8;        // n8 groups per warp (8 or 4)
    constexpr int ASZ = BM * 128, BSZ = BN * 128, STG = ASZ + BSZ;

    extern __shared__ __align__(1024) char smraw[];
    const uint32_t sb = smem_u32(smraw);
    const int tid = threadIdx.x, w = tid >> 5, lane = tid & 31;
    const int wm = w & 3, wn = w >> 2;
    const int bm = blockIdx.y * BM, bn = blockIdx.x * BN;

    auto load = [&](int c) {
        const uint32_t st = sb + (c & 1) * STG;
        const __nv_bfloat16* Ap = (c >= 4 && c < 8) ? Alo : Ahi;
        const __nv_bfloat16* Bp = (c < 8) ? Bhi : Blo;
        const int ko = (c & 3) * 64;
        for (int t = tid; t < BM * 8; t += 256) {
            int r = t >> 3, q = t & 7;
            int gr = bm + r; if (gr >= NN) gr = NN - 1;
            cp_async16(st + SW128(r * 128 + q * 16), Ap + (size_t)gr * 256 + ko + q * 8);
        }
        for (int t = tid; t < BN * 8; t += 256) {
            int r = t >> 3, q = t & 7;
            cp_async16(st + ASZ + SW128(r * 128 + q * 16), Bp + (size_t)(bn + r) * 256 + ko + q * 8);
        }
        asm volatile("cp.async.commit_group;" ::: "memory");
    };

    load(0);
    load(1);

    float acc[2][NG][4] = {};
    // ldmatrix lane-address components (constant across chunks)
    const int a_row = wm * 32 + (lane & 7) + ((lane >> 3) & 1) * 8;  // + f*16
    const int a_colq = (lane >> 4) * 16;                             // + kk*32
    const int b_row = wn * WN + (lane >> 4) * 8 + (lane & 7);        // + g16*16
    const int b_colq = ((lane >> 3) & 1) * 16;                       // + kk*32

    for (int c = 0; c < 12; ++c) {
        const uint32_t st = sb + (c & 1) * STG;
        if (c < 11) asm volatile("cp.async.wait_group 1;" ::: "memory");
        else        asm volatile("cp.async.wait_group 0;" ::: "memory");
        __syncthreads();
#pragma unroll
        for (int kk = 0; kk < 4; ++kk) {
            uint32_t a[8];
#pragma unroll
            for (int f = 0; f < 2; ++f)
                ldsm_x4(a[f * 4], a[f * 4 + 1], a[f * 4 + 2], a[f * 4 + 3],
                        st + SW128((a_row + f * 16) * 128 + kk * 32 + a_colq));
            uint32_t b[NG * 2];
#pragma unroll
            for (int g = 0; g < NG / 2; ++g)
                ldsm_x4(b[g * 4], b[g * 4 + 1], b[g * 4 + 2], b[g * 4 + 3],
                        st + ASZ + SW128((b_row + g * 16) * 128 + kk * 32 + b_colq));
#pragma unroll
            for (int f = 0; f < 2; ++f)
#pragma unroll
                for (int g = 0; g < NG; ++g)
                    mma16816(acc[f][g], a + f * 4, b + g * 2);
        }
        __syncthreads();
        if (c + 2 < 12) load(c + 2);
    }

    // epilogue: C frag rows l/4 and l/4+8, cols (l%4)*2,+1
#pragma unroll
    for (int f = 0; f < 2; ++f) {
#pragma unroll
        for (int g = 0; g < NG; ++g) {
            int m = bm + wm * 32 + f * 16 + (lane >> 2);
            int n = bn + wn * WN + g * 8 + (lane & 3) * 2;
            if (m < NN)
                *(float2*)(C + (size_t)m * NO + n) = make_float2(acc[f][g][0], acc[f][g][1]);
            if (m + 8 < NN)
                *(float2*)(C + (size_t)(m + 8) * NO + n) = make_float2(acc[f][g][2], acc[f][g][3]);
        }
    }
}

// ---------------- CSR build ------------------------------------------------------
__global__ void k_zero_cnt() {
    int i = blockIdx.x * blockDim.x + threadIdx.x;
    if (i < NN) g_cnt[i] = 0;
}
__global__ void k_count(const int* __restrict__ ei) {
    int e = blockIdx.x * blockDim.x + threadIdx.x;
    if (e >= ET) return;
    int d = (e < EE) ? ei[EE + e] : (e - EE);
    atomicAdd(&g_cnt[d], 1);
}
__global__ void k_scan1() {
    __shared__ int sh[SCAN_B];
    int tid = threadIdx.x;
    int i = blockIdx.x * SCAN_B + tid;
    int v = (i < NN) ? g_cnt[i] : 0;
    sh[tid] = v;
    __syncthreads();
    for (int off = 1; off < SCAN_B; off <<= 1) {
        int t = (tid >= off) ? sh[tid - off] : 0;
        __syncthreads();
        sh[tid] += t;
        __syncthreads();
    }
    g_incl[i] = sh[tid];
    if (tid == SCAN_B - 1) g_bsum[blockIdx.x] = sh[tid];
}
__global__ void k_scan2() {
    if (threadIdx.x == 0) {
        int s = 0;
        for (int i = 0; i < NBLK; ++i) { int t = g_bsum[i]; g_bsum[i] = s; s += t; }
    }
}
__global__ void k_scan3() {
    int i = blockIdx.x * blockDim.x + threadIdx.x;
    if (i < NN) {
        int v = g_cnt[i];
        int ex = g_incl[i] - v + g_bsum[i >> 10];
        g_rowptr[i] = ex;
        g_fill[i] = ex;
    }
    if (i == 0) g_rowptr[NN] = ET;
}
__global__ void k_fill(const int* __restrict__ ei) {
    int e = blockIdx.x * blockDim.x + threadIdx.x;
    if (e >= ET) return;
    int s, d;
    if (e < EE) { s = ei[e]; d = ei[EE + e]; }
    else        { s = e - EE; d = s; }
    int pos = atomicAdd(&g_fill[d], 1);
    g_col[pos] = s;
}

// ---------------- per-node attention logits --------------------------------------
template <int HEADS>
__global__ __launch_bounds__(256) void k_alpha(const float* __restrict__ h,
                                               const float* __restrict__ a_s,
                                               const float* __restrict__ a_d,
                                               float* __restrict__ as_out,
                                               float* __restrict__ ad_out) {
    int warp = (blockIdx.x * blockDim.x + threadIdx.x) >> 5;
    int lane = threadIdx.x & 31;
    if (warp >= NN) return;
    const float* hr = h + (size_t)warp * HEADS * 64;
#pragma unroll
    for (int hh = 0; hh < HEADS; ++hh) {
        float v0 = hr[hh * 64 + lane], v1 = hr[hh * 64 + lane + 32];
        float ps = v0 * a_s[hh * 64 + lane] + v1 * a_s[hh * 64 + lane + 32];
        float pd = v0 * a_d[hh * 64 + lane] + v1 * a_d[hh * 64 + lane + 32];
#pragma unroll
        for (int o = 16; o; o >>= 1) {
            ps += __shfl_xor_sync(0xffffffffu, ps, o);
            pd += __shfl_xor_sync(0xffffffffu, pd, o);
        }
        if (lane == 0) { as_out[warp * HEADS + hh] = ps; ad_out[warp * HEADS + hh] = pd; }
    }
}

// ---------------- GAT conv -------------------------------------------------------
template <int HEADS, bool RELU, bool SPLIT>
__global__ __launch_bounds__(256) void k_conv(const float* __restrict__ h,
                                              const float* __restrict__ as_,
                                              const float* __restrict__ ad_,
                                              const float* __restrict__ bias,
                                              float* __restrict__ out,
                                              __nv_bfloat16* __restrict__ ohi,
                                              __nv_bfloat16* __restrict__ olo) {
    const int TC = HEADS * 64;
    const int NPL = TC / 32;
    int warp = (blockIdx.x * blockDim.x + threadIdx.x) >> 5;
    int lane = threadIdx.x & 31;
    if (warp >= NN) return;
    int beg = g_rowptr[warp], end = g_rowptr[warp + 1];

    float adh[HEADS];
#pragma unroll
    for (int hh = 0; hh < HEADS; ++hh) adh[hh] = ad_[warp * HEADS + hh];

    float mx[HEADS];
#pragma unroll
    for (int hh = 0; hh < HEADS; ++hh) mx[hh] = -1e30f;
    for (int i = beg + lane; i < end; i += 32) {
        int s = g_col[i];
#pragma unroll
        for (int hh = 0; hh < HEADS; ++hh) {
            float e = as_[s * HEADS + hh] + adh[hh];
            e = e > 0.f ? e : 0.2f * e;
            mx[hh] = fmaxf(mx[hh], e);
        }
    }
#pragma unroll
    for (int hh = 0; hh < HEADS; ++hh)
#pragma unroll
        for (int o = 16; o; o >>= 1)
            mx[hh] = fmaxf(mx[hh], __shfl_xor_sync(0xffffffffu, mx[hh], o));

    float sm[HEADS] = {};
    for (int i = beg + lane; i < end; i += 32) {
        int s = g_col[i];
#pragma unroll
        for (int hh = 0; hh < HEADS; ++hh) {
            float e = as_[s * HEADS + hh] + adh[hh];
            e = e > 0.f ? e : 0.2f * e;
            sm[hh] += __expf(e - mx[hh]);
        }
    }
#pragma unroll
    for (int hh = 0; hh < HEADS; ++hh)
#pragma unroll
        for (int o = 16; o; o >>= 1)
            sm[hh] += __shfl_xor_sync(0xffffffffu, sm[hh], o);

    const int myhead = (lane * NPL) / 64;
    float mm = mx[myhead], adm = adh[myhead], inv = 1.f / sm[myhead];
    float acc[NPL] = {};
    for (int i = beg; i < end; ++i) {
        int s = g_col[i];
        float e = as_[s * HEADS + myhead] + adm;
        e = e > 0.f ? e : 0.2f * e;
        float w = __expf(e - mm) * inv;
        const float* hp = h + (size_t)s * TC + lane * NPL;
        if constexpr (NPL == 8) {
            float4 x0 = *(const float4*)hp;
            float4 x1 = *(const float4*)(hp + 4);
            acc[0] += w * x0.x; acc[1] += w * x0.y; acc[2] += w * x0.z; acc[3] += w * x0.w;
            acc[4] += w * x1.x; acc[5] += w * x1.y; acc[6] += w * x1.z; acc[7] += w * x1.w;
        } else {
            float2 x0 = *(const float2*)hp;
            acc[0] += w * x0.x; acc[1] += w * x0.y;
        }
    }
    float dinv = 1.f / (float)(end - beg);
    float v[NPL];
#pragma unroll
    for (int j = 0; j < NPL; ++j) {
        v[j] = acc[j] * dinv + bias[lane * NPL + j];
        if (RELU) v[j] = fmaxf(v[j], 0.f);
    }
    if constexpr (SPLIT) {
        __nv_bfloat162 vh[NPL / 2], vl[NPL / 2];
#pragma unroll
        for (int j = 0; j < NPL / 2; ++j) {
            __nv_bfloat16 h0 = __float2bfloat16(v[2 * j]);
            __nv_bfloat16 h1 = __float2bfloat16(v[2 * j + 1]);
            vh[j] = __nv_bfloat162(h0, h1);
            vl[j] = __nv_bfloat162(__float2bfloat16(v[2 * j] - __bfloat162float(h0)),
                                   __float2bfloat16(v[2 * j + 1] - __bfloat162float(h1)));
        }
        size_t base = (size_t)warp * TC + lane * NPL;
        *(uint4*)(ohi + base) = *(uint4*)vh;
        *(uint4*)(olo + base) = *(uint4*)vl;
    } else {
#pragma unroll
        for (int j = 0; j < NPL; ++j)
            out[(size_t)warp * TC + lane * NPL + j] = v[j];
    }
}

// ---------------- launch ---------------------------------------------------------
extern "C" void kernel_launch(void* const* d_in, const int* in_sizes, int n_in,
                              void* d_out, int out_size) {
    const float* x   = (const float*)d_in[0];
    const int*   ei  = (const int*)d_in[1];
    const float* W0  = (const float*)d_in[2];
    const float* a0s = (const float*)d_in[3];
    const float* a0d = (const float*)d_in[4];
    const float* b0  = (const float*)d_in[5];
    const float* W1  = (const float*)d_in[6];
    const float* a1s = (const float*)d_in[7];
    const float* a1d = (const float*)d_in[8];
    const float* b1  = (const float*)d_in[9];
    const float* W2  = (const float*)d_in[10];
    const float* a2s = (const float*)d_in[11];
    const float* a2d = (const float*)d_in[12];
    const float* b2  = (const float*)d_in[13];
    float* out = (float*)d_out;

    void* p;
    cudaGetSymbolAddress(&p, g_h);    float* hbuf = (float*)p;
    cudaGetSymbolAddress(&p, g_ahi);  __nv_bfloat16* ahi = (__nv_bfloat16*)p;
    cudaGetSymbolAddress(&p, g_alo);  __nv_bfloat16* alo = (__nv_bfloat16*)p;
    cudaGetSymbolAddress(&p, g_w0hi); __nv_bfloat16* w0hi = (__nv_bfloat16*)p;
    cudaGetSymbolAddress(&p, g_w0lo); __nv_bfloat16* w0lo = (__nv_bfloat16*)p;
    cudaGetSymbolAddress(&p, g_w1hi); __nv_bfloat16* w1hi = (__nv_bfloat16*)p;
    cudaGetSymbolAddress(&p, g_w1lo); __nv_bfloat16* w1lo = (__nv_bfloat16*)p;
    cudaGetSymbolAddress(&p, g_w2hi); __nv_bfloat16* w2hi = (__nv_bfloat16*)p;
    cudaGetSymbolAddress(&p, g_w2lo); __nv_bfloat16* w2lo = (__nv_bfloat16*)p;
    cudaGetSymbolAddress(&p, g_as);   float* asb = (float*)p;
    cudaGetSymbolAddress(&p, g_ad);   float* adb = (float*)p;

    const int SMEM256 = 2 * (128 * 128 + 128 * 128);  // 65536
    const int SMEM64  = 2 * (128 * 128 + 64 * 128);   // 49152
    static bool attr_done = false;
    if (!attr_done) {
        cudaFuncSetAttribute(k_gemm_mma<256>, cudaFuncAttributeMaxDynamicSharedMemorySize, SMEM256);
        cudaFuncSetAttribute(k_gemm_mma<64>,  cudaFuncAttributeMaxDynamicSharedMemorySize, SMEM64);
        attr_done = true;
    }

    const int WPB = 8;
    const int NODE_BLKS = (NN + WPB - 1) / WPB;
    dim3 g256(2, (NN + 127) / 128);
    dim3 g64(1, (NN + 127) / 128);

    // launches 1-5 (profiled launch #6 is the first GEMM)
    k_split_x<<<(NN * 64 + 255) / 256, 256>>>(x);
    k_split_wt<256><<<(256 * 256 + 255) / 256, 256>>>(W0, w0hi, w0lo);
    k_split_wt<256><<<(256 * 256 + 255) / 256, 256>>>(W1, w1hi, w1lo);
    k_split_wt<64><<<(256 * 64 + 255) / 256, 256>>>(W2, w2hi, w2lo);
    k_zero_cnt<<<(NN + 255) / 256, 256>>>();

    // layer-0 GEMM (tensor pipe, hi/lo split)
    k_gemm_mma<256><<<g256, 256, SMEM256>>>(ahi, alo, w0hi, w0lo, hbuf);

    // CSR build
    k_count<<<(ET + 255) / 256, 256>>>(ei);
    k_scan1<<<NBLK, SCAN_B>>>();
    k_scan2<<<1, 32>>>();
    k_scan3<<<(NN + 255) / 256, 256>>>();
    k_fill<<<(ET + 255) / 256, 256>>>(ei);

    // layer 0 attention + conv (conv writes bf16 hi/lo for next GEMM)
    k_alpha<4><<<NODE_BLKS, 256>>>(hbuf, a0s, a0d, asb, adb);
    k_conv<4, true, true><<<NODE_BLKS, 256>>>(hbuf, asb, adb, b0, nullptr, ahi, alo);

    // layer 1
    k_gemm_mma<256><<<g256, 256, SMEM256>>>(ahi, alo, w1hi, w1lo, hbuf);
    k_alpha<4><<<NODE_BLKS, 256>>>(hbuf, a1s, a1d, asb, adb);
    k_conv<4, true, true><<<NODE_BLKS, 256>>>(hbuf, asb, adb, b1, nullptr, ahi, alo);

    // layer 2 (heads=1) -> final output fp32
    k_gemm_mma<64><<<g64, 256, SMEM64>>>(ahi, alo, w2hi, w2lo, hbuf);
    k_alpha<1><<<NODE_BLKS, 256>>>(hbuf, a2s, a2d, asb, adb);
    k_conv<1, false, false><<<NODE_BLKS, 256>>>(hbuf, asb, adb, b2, out, nullptr, nullptr);
}

// round 4
// speedup vs baseline: 1.8047x; 1.0733x over previous
#include <cuda_runtime.h>
#include <cuda_fp16.h>
#include <cstdint>

#define NN 50000
#define EE 600000
#define ET (EE + NN)
#define KDIM 256
#define SCAN_B 1024
#define NBLK ((NN + SCAN_B - 1) / SCAN_B)

// ---------------- scratch (device globals; no allocation allowed) ----------------
__device__ __half g_ahi[(size_t)NN * 256];  // GEMM A operand (layer input), hi
__device__ __half g_alo[(size_t)NN * 256];  // lo
__device__ __half g_hhi[(size_t)NN * 256];  // GEMM output (pre-aggregation), hi
__device__ __half g_hlo[(size_t)NN * 256];  // lo
__device__ __half g_w0hi[256 * 256], g_w0lo[256 * 256];  // Wt [NO,K]
__device__ __half g_w1hi[256 * 256], g_w1lo[256 * 256];
__device__ __half g_w2hi[64 * 256],  g_w2lo[64 * 256];
__device__ float g_as[NN * 4];
__device__ float g_ad[NN * 4];
__device__ int   g_cnt[NN];
__device__ int   g_incl[NBLK * SCAN_B];
__device__ int   g_bsum[NBLK];
__device__ int   g_rowptr[NN + 1];
__device__ int   g_fill[NN];
__device__ int   g_col[ET];

// ---------------- PTX helpers ----------------------------------------------------
__device__ __forceinline__ uint32_t smem_u32(const void* p) {
    uint32_t a;
    asm("{ .reg .u64 t; cvta.to.shared.u64 t, %1; cvt.u32.u64 %0, t; }" : "=r"(a) : "l"(p));
    return a;
}
__device__ __forceinline__ void cp_async16(uint32_t dst, const void* src) {
    asm volatile("cp.async.cg.shared.global [%0], [%1], 16;"
                 :: "r"(dst), "l"(__cvta_generic_to_global(src)) : "memory");
}
__device__ __forceinline__ void ldsm_x4(uint32_t& r0, uint32_t& r1, uint32_t& r2,
                                        uint32_t& r3, uint32_t addr) {
    asm volatile("ldmatrix.sync.aligned.m8n8.x4.shared.b16 {%0,%1,%2,%3}, [%4];"
                 : "=r"(r0), "=r"(r1), "=r"(r2), "=r"(r3) : "r"(addr));
}
__device__ __forceinline__ void mma16816(float* c, const uint32_t* a, const uint32_t* b) {
    asm volatile("mma.sync.aligned.m16n8k16.row.col.f32.f16.f16.f32 "
                 "{%0,%1,%2,%3}, {%4,%5,%6,%7}, {%8,%9}, {%0,%1,%2,%3};"
                 : "+f"(c[0]), "+f"(c[1]), "+f"(c[2]), "+f"(c[3])
                 : "r"(a[0]), "r"(a[1]), "r"(a[2]), "r"(a[3]), "r"(b[0]), "r"(b[1]));
}
#define SW128(o) ((o) ^ (((o) >> 3) & 0x70))

__device__ __forceinline__ void split2(float v, __half& hi, __half& lo) {
    hi = __float2half_rn(v);
    lo = __float2half_rn(v - __half2float(hi));
}

// ---------------- split conversions ----------------------------------------------
__global__ void k_split_x(const float* __restrict__ x) {
    int i = blockIdx.x * blockDim.x + threadIdx.x;  // one float4
    if (i >= NN * 64) return;
    float4 v = ((const float4*)x)[i];
    __half h0, h1, h2, h3, l0, l1, l2, l3;
    split2(v.x, h0, l0); split2(v.y, h1, l1);
    split2(v.z, h2, l2); split2(v.w, h3, l3);
    ((__half2*)g_ahi)[2 * i]     = __halves2half2(h0, h1);
    ((__half2*)g_ahi)[2 * i + 1] = __halves2half2(h2, h3);
    ((__half2*)g_alo)[2 * i]     = __halves2half2(l0, l1);
    ((__half2*)g_alo)[2 * i + 1] = __halves2half2(l2, l3);
}

template <int NO>
__global__ void k_split_wt(const float* __restrict__ W, __half* __restrict__ hi,
                           __half* __restrict__ lo) {
    int i = blockIdx.x * blockDim.x + threadIdx.x;
    if (i >= 256 * NO) return;
    int k = i / NO, n = i % NO;
    __half h, l;
    split2(W[i], h, l);
    hi[n * 256 + k] = h;
    lo[n * 256 + k] = l;
}

// ---------------- mma.sync GEMM: hi/lo split, epilogue emits fp16 hi/lo ----------
// Virtual K = 768: chunks 0-3 Ahi*Bhi, 4-7 Alo*Bhi, 8-11 Ahi*Blo (lo*lo dropped).
template <int NO>
__global__ __launch_bounds__(256) void k_gemm_mma(const __half* __restrict__ Ahi,
                                                  const __half* __restrict__ Alo,
                                                  const __half* __restrict__ Bhi,
                                                  const __half* __restrict__ Blo,
                                                  __half* __restrict__ Hhi,
                                                  __half* __restrict__ Hlo) {
    constexpr int BM = 128, BN = (NO == 256) ? 128 : 64;
    constexpr int WN = BN / 2;        // warp tile: 32 x WN (warp grid 4x2)
    constexpr int NG = WN / 8;
    constexpr int ASZ = BM * 128, BSZ = BN * 128, STG = ASZ + BSZ;

    extern __shared__ __align__(1024) char smraw[];
    const uint32_t sb = smem_u32(smraw);
    const int tid = threadIdx.x, w = tid >> 5, lane = tid & 31;
    const int wm = w & 3, wn = w >> 2;
    const int bm = blockIdx.y * BM, bn = blockIdx.x * BN;

    auto load = [&](int c) {
        const uint32_t st = sb + (c & 1) * STG;
        const __half* Ap = (c >= 4 && c < 8) ? Alo : Ahi;
        const __half* Bp = (c < 8) ? Bhi : Blo;
        const int ko = (c & 3) * 64;
        for (int t = tid; t < BM * 8; t += 256) {
            int r = t >> 3, q = t & 7;
            int gr = bm + r; if (gr >= NN) gr = NN - 1;
            cp_async16(st + SW128(r * 128 + q * 16), Ap + (size_t)gr * 256 + ko + q * 8);
        }
        for (int t = tid; t < BN * 8; t += 256) {
            int r = t >> 3, q = t & 7;
            cp_async16(st + ASZ + SW128(r * 128 + q * 16), Bp + (size_t)(bn + r) * 256 + ko + q * 8);
        }
        asm volatile("cp.async.commit_group;" ::: "memory");
    };

    load(0);
    load(1);

    float acc[2][NG][4] = {};
    const int a_row = wm * 32 + (lane & 7) + ((lane >> 3) & 1) * 8;
    const int a_colq = (lane >> 4) * 16;
    const int b_row = wn * WN + (lane >> 4) * 8 + (lane & 7);
    const int b_colq = ((lane >> 3) & 1) * 16;

    for (int c = 0; c < 12; ++c) {
        const uint32_t st = sb + (c & 1) * STG;
        if (c < 11) asm volatile("cp.async.wait_group 1;" ::: "memory");
        else        asm volatile("cp.async.wait_group 0;" ::: "memory");
        __syncthreads();
#pragma unroll
        for (int kk = 0; kk < 4; ++kk) {
            uint32_t a[8];
#pragma unroll
            for (int f = 0; f < 2; ++f)
                ldsm_x4(a[f * 4], a[f * 4 + 1], a[f * 4 + 2], a[f * 4 + 3],
                        st + SW128((a_row + f * 16) * 128 + kk * 32 + a_colq));
            uint32_t b[NG * 2];
#pragma unroll
            for (int g = 0; g < NG / 2; ++g)
                ldsm_x4(b[g * 4], b[g * 4 + 1], b[g * 4 + 2], b[g * 4 + 3],
                        st + ASZ + SW128((b_row + g * 16) * 128 + kk * 32 + b_colq));
#pragma unroll
            for (int f = 0; f < 2; ++f)
#pragma unroll
                for (int g = 0; g < NG; ++g)
                    mma16816(acc[f][g], a + f * 4, b + g * 2);
        }
        __syncthreads();
        if (c + 2 < 12) load(c + 2);
    }

    // epilogue: split fp32 acc -> fp16 hi/lo
#pragma unroll
    for (int f = 0; f < 2; ++f) {
#pragma unroll
        for (int g = 0; g < NG; ++g) {
            int m = bm + wm * 32 + f * 16 + (lane >> 2);
            int n = bn + wn * WN + g * 8 + (lane & 3) * 2;
#pragma unroll
            for (int rr = 0; rr < 2; ++rr) {
                int mm = m + rr * 8;
                if (mm < NN) {
                    __half h0, h1, l0, l1;
                    split2(acc[f][g][rr * 2 + 0], h0, l0);
                    split2(acc[f][g][rr * 2 + 1], h1, l1);
                    *(__half2*)(Hhi + (size_t)mm * NO + n) = __halves2half2(h0, h1);
                    *(__half2*)(Hlo + (size_t)mm * NO + n) = __halves2half2(l0, l1);
                }
            }
        }
    }
}

// ---------------- CSR build ------------------------------------------------------
__global__ void k_zero_cnt() {
    int i = blockIdx.x * blockDim.x + threadIdx.x;
    if (i < NN) g_cnt[i] = 0;
}
__global__ void k_count(const int* __restrict__ ei) {
    int e = blockIdx.x * blockDim.x + threadIdx.x;
    if (e >= ET) return;
    int d = (e < EE) ? ei[EE + e] : (e - EE);
    atomicAdd(&g_cnt[d], 1);
}
__global__ void k_scan1() {
    __shared__ int sh[SCAN_B];
    int tid = threadIdx.x;
    int i = blockIdx.x * SCAN_B + tid;
    int v = (i < NN) ? g_cnt[i] : 0;
    sh[tid] = v;
    __syncthreads();
    for (int off = 1; off < SCAN_B; off <<= 1) {
        int t = (tid >= off) ? sh[tid - off] : 0;
        __syncthreads();
        sh[tid] += t;
        __syncthreads();
    }
    g_incl[i] = sh[tid];
    if (tid == SCAN_B - 1) g_bsum[blockIdx.x] = sh[tid];
}
__global__ void k_scan2() {
    if (threadIdx.x == 0) {
        int s = 0;
        for (int i = 0; i < NBLK; ++i) { int t = g_bsum[i]; g_bsum[i] = s; s += t; }
    }
}
__global__ void k_scan3() {
    int i = blockIdx.x * blockDim.x + threadIdx.x;
    if (i < NN) {
        int v = g_cnt[i];
        int ex = g_incl[i] - v + g_bsum[i >> 10];
        g_rowptr[i] = ex;
        g_fill[i] = ex;
    }
    if (i == 0) g_rowptr[NN] = ET;
}
__global__ void k_fill(const int* __restrict__ ei) {
    int e = blockIdx.x * blockDim.x + threadIdx.x;
    if (e >= ET) return;
    int s, d;
    if (e < EE) { s = ei[e]; d = ei[EE + e]; }
    else        { s = e - EE; d = s; }
    int pos = atomicAdd(&g_fill[d], 1);
    g_col[pos] = s;
}

// ---------------- per-node attention logits (reads hi+lo, fp32 reconstruct) ------
template <int HEADS>
__global__ __launch_bounds__(256) void k_alpha(const float* __restrict__ a_s,
                                               const float* __restrict__ a_d,
                                               float* __restrict__ as_out,
                                               float* __restrict__ ad_out) {
    int warp = (blockIdx.x * blockDim.x + threadIdx.x) >> 5;
    int lane = threadIdx.x & 31;
    if (warp >= NN) return;
    const __half2* hr = (const __half2*)(g_hhi + (size_t)warp * HEADS * 64);
    const __half2* lr = (const __half2*)(g_hlo + (size_t)warp * HEADS * 64);
#pragma unroll
    for (int hh = 0; hh < HEADS; ++hh) {
        float2 hf = __half22float2(hr[hh * 32 + lane]);
        float2 lf = __half22float2(lr[hh * 32 + lane]);
        float v0 = hf.x + lf.x, v1 = hf.y + lf.y;
        float s0 = a_s[hh * 64 + 2 * lane], s1 = a_s[hh * 64 + 2 * lane + 1];
        float d0 = a_d[hh * 64 + 2 * lane], d1 = a_d[hh * 64 + 2 * lane + 1];
        float ps = v0 * s0 + v1 * s1;
        float pd = v0 * d0 + v1 * d1;
#pragma unroll
        for (int o = 16; o; o >>= 1) {
            ps += __shfl_xor_sync(0xffffffffu, ps, o);
            pd += __shfl_xor_sync(0xffffffffu, pd, o);
        }
        if (lane == 0) { as_out[warp * HEADS + hh] = ps; ad_out[warp * HEADS + hh] = pd; }
    }
}

// ---------------- GAT conv: online softmax + fp16 message gather -----------------
template <int HEADS, bool RELU, bool SPLIT>
__global__ __launch_bounds__(256) void k_conv(const float* __restrict__ as_,
                                              const float* __restrict__ ad_,
                                              const float* __restrict__ bias,
                                              float* __restrict__ out,
                                              __half* __restrict__ ohi,
                                              __half* __restrict__ olo) {
    const int TC = HEADS * 64;
    const int NPL = TC / 32;  // 8 (H=4) or 2 (H=1)
    int warp = (blockIdx.x * blockDim.x + threadIdx.x) >> 5;
    int lane = threadIdx.x & 31;
    if (warp >= NN) return;
    int beg = g_rowptr[warp], end = g_rowptr[warp + 1];

    float adh[HEADS];
#pragma unroll
    for (int hh = 0; hh < HEADS; ++hh) adh[hh] = ad_[warp * HEADS + hh];

    // single pass: online softmax (m, s) per head per lane
    float mx[HEADS], sm[HEADS];
#pragma unroll
    for (int hh = 0; hh < HEADS; ++hh) { mx[hh] = -1e30f; sm[hh] = 0.f; }
    for (int i = beg + lane; i < end; i += 32) {
        int s = g_col[i];
#pragma unroll
        for (int hh = 0; hh < HEADS; ++hh) {
            float e = as_[s * HEADS + hh] + adh[hh];
            e = e > 0.f ? e : 0.2f * e;
            if (e > mx[hh]) {
                sm[hh] = sm[hh] * __expf(mx[hh] - e) + 1.f;
                mx[hh] = e;
            } else {
                sm[hh] += __expf(e - mx[hh]);
            }
        }
    }
#pragma unroll
    for (int hh = 0; hh < HEADS; ++hh) {
#pragma unroll
        for (int o = 16; o; o >>= 1) {
            float mo = __shfl_xor_sync(0xffffffffu, mx[hh], o);
            float so = __shfl_xor_sync(0xffffffffu, sm[hh], o);
            float mn = fmaxf(mx[hh], mo);
            sm[hh] = sm[hh] * __expf(mx[hh] - mn) + so * __expf(mo - mn);
            mx[hh] = mn;
        }
    }

    // weighted gather: lane owns NPL contiguous channels; messages = fp16 hi
    const int myhead = (lane * NPL) / 64;
    float mm = mx[myhead], adm = adh[myhead], inv = 1.f / sm[myhead];
    float acc[NPL] = {};
    for (int i = beg; i < end; ++i) {
        int s = g_col[i];
        float e = as_[s * HEADS + myhead] + adm;
        e = e > 0.f ? e : 0.2f * e;
        float w = __expf(e - mm) * inv;
        const __half* hp = g_hhi + (size_t)s * TC + lane * NPL;
        if constexpr (NPL == 8) {
            uint4 raw = *(const uint4*)hp;
            float2 f0 = __half22float2(*(__half2*)&raw.x);
            float2 f1 = __half22float2(*(__half2*)&raw.y);
            float2 f2 = __half22float2(*(__half2*)&raw.z);
            float2 f3 = __half22float2(*(__half2*)&raw.w);
            acc[0] += w * f0.x; acc[1] += w * f0.y; acc[2] += w * f1.x; acc[3] += w * f1.y;
            acc[4] += w * f2.x; acc[5] += w * f2.y; acc[6] += w * f3.x; acc[7] += w * f3.y;
        } else {
            uint32_t raw = *(const uint32_t*)hp;
            float2 f0 = __half22float2(*(__half2*)&raw);
            acc[0] += w * f0.x; acc[1] += w * f0.y;
        }
    }
    float dinv = 1.f / (float)(end - beg);
    float v[NPL];
#pragma unroll
    for (int j = 0; j < NPL; ++j) {
        v[j] = acc[j] * dinv + bias[lane * NPL + j];
        if (RELU) v[j] = fmaxf(v[j], 0.f);
    }
    if constexpr (SPLIT) {
        __half2 vh[NPL / 2], vl[NPL / 2];
#pragma unroll
        for (int j = 0; j < NPL / 2; ++j) {
            __half h0, h1, l0, l1;
            split2(v[2 * j], h0, l0);
            split2(v[2 * j + 1], h1, l1);
            vh[j] = __halves2half2(h0, h1);
            vl[j] = __halves2half2(l0, l1);
        }
        size_t base = (size_t)warp * TC + lane * NPL;
        *(uint4*)(ohi + base) = *(uint4*)vh;
        *(uint4*)(olo + base) = *(uint4*)vl;
    } else {
#pragma unroll
        for (int j = 0; j < NPL; ++j)
            out[(size_t)warp * TC + lane * NPL + j] = v[j];
    }
}

// ---------------- launch ---------------------------------------------------------
extern "C" void kernel_launch(void* const* d_in, const int* in_sizes, int n_in,
                              void* d_out, int out_size) {
    const float* x   = (const float*)d_in[0];
    const int*   ei  = (const int*)d_in[1];
    const float* W0  = (const float*)d_in[2];
    const float* a0s = (const float*)d_in[3];
    const float* a0d = (const float*)d_in[4];
    const float* b0  = (const float*)d_in[5];
    const float* W1  = (const float*)d_in[6];
    const float* a1s = (const float*)d_in[7];
    const float* a1d = (const float*)d_in[8];
    const float* b1  = (const float*)d_in[9];
    const float* W2  = (const float*)d_in[10];
    const float* a2s = (const float*)d_in[11];
    const float* a2d = (const float*)d_in[12];
    const float* b2  = (const float*)d_in[13];
    float* out = (float*)d_out;

    void* p;
    cudaGetSymbolAddress(&p, g_ahi);  __half* ahi = (__half*)p;
    cudaGetSymbolAddress(&p, g_alo);  __half* alo = (__half*)p;
    cudaGetSymbolAddress(&p, g_hhi);  __half* hhi = (__half*)p;
    cudaGetSymbolAddress(&p, g_hlo);  __half* hlo = (__half*)p;
    cudaGetSymbolAddress(&p, g_w0hi); __half* w0hi = (__half*)p;
    cudaGetSymbolAddress(&p, g_w0lo); __half* w0lo = (__half*)p;
    cudaGetSymbolAddress(&p, g_w1hi); __half* w1hi = (__half*)p;
    cudaGetSymbolAddress(&p, g_w1lo); __half* w1lo = (__half*)p;
    cudaGetSymbolAddress(&p, g_w2hi); __half* w2hi = (__half*)p;
    cudaGetSymbolAddress(&p, g_w2lo); __half* w2lo = (__half*)p;
    cudaGetSymbolAddress(&p, g_as);   float* asb = (float*)p;
    cudaGetSymbolAddress(&p, g_ad);   float* adb = (float*)p;

    const int SMEM256 = 2 * (128 * 128 + 128 * 128);  // 65536
    const int SMEM64  = 2 * (128 * 128 + 64 * 128);   // 49152
    static bool attr_done = false;
    if (!attr_done) {
        cudaFuncSetAttribute(k_gemm_mma<256>, cudaFuncAttributeMaxDynamicSharedMemorySize, SMEM256);
        cudaFuncSetAttribute(k_gemm_mma<64>,  cudaFuncAttributeMaxDynamicSharedMemorySize, SMEM64);
        attr_done = true;
    }

    const int WPB = 8;
    const int NODE_BLKS = (NN + WPB - 1) / WPB;
    dim3 g256(2, (NN + 127) / 128);
    dim3 g64(1, (NN + 127) / 128);

    // launches 1-3; launch #4 (profiled) is the layer-0 GEMM
    k_split_x<<<(NN * 64 + 255) / 256, 256>>>(x);
    k_split_wt<256><<<(256 * 256 + 255) / 256, 256>>>(W0, w0hi, w0lo);
    k_zero_cnt<<<(NN + 255) / 256, 256>>>();
    k_gemm_mma<256><<<g256, 256, SMEM256>>>(ahi, alo, w0hi, w0lo, hhi, hlo);

    // CSR build (overlaps conceptually; sequential is fine)
    k_count<<<(ET + 255) / 256, 256>>>(ei);
    k_scan1<<<NBLK, SCAN_B>>>();
    k_scan2<<<1, 32>>>();
    k_scan3<<<(NN + 255) / 256, 256>>>();
    k_fill<<<(ET + 255) / 256, 256>>>(ei);

    // layer 0 attention + conv (conv emits fp16 hi/lo for next GEMM)
    k_alpha<4><<<NODE_BLKS, 256>>>(a0s, a0d, asb, adb);
    k_conv<4, true, true><<<NODE_BLKS, 256>>>(asb, adb, b0, nullptr, ahi, alo);

    // layer 1
    k_split_wt<256><<<(256 * 256 + 255) / 256, 256>>>(W1, w1hi, w1lo);
    k_gemm_mma<256><<<g256, 256, SMEM256>>>(ahi, alo, w1hi, w1lo, hhi, hlo);
    k_alpha<4><<<NODE_BLKS, 256>>>(a1s, a1d, asb, adb);
    k_conv<4, true, true><<<NODE_BLKS, 256>>>(asb, adb, b1, nullptr, ahi, alo);

    // layer 2 (heads=1) -> final output fp32
    k_split_wt<64><<<(256 * 64 + 255) / 256, 256>>>(W2, w2hi, w2lo);
    k_gemm_mma<64><<<g64, 256, SMEM64>>>(ahi, alo, w2hi, w2lo, hhi, hlo);
    k_alpha<1><<<NODE_BLKS, 256>>>(a2s, a2d, asb, adb);
    k_conv<1, false, false><<<NODE_BLKS, 256>>>(asb, adb, b2, out, nullptr, nullptr);
}

// round 5
// speedup vs baseline: 2.0196x; 1.1190x over previous
#include <cuda_runtime.h>
#include <cuda_fp16.h>
#include <cstdint>

#define NN 50000
#define EE 600000
#define ET (EE + NN)
#define SCAN_B 1024
#define NBLK ((NN + SCAN_B - 1) / SCAN_B)

// ---------------- scratch ---------------------------------------------------------
__device__ __half g_ahi[(size_t)NN * 256];
__device__ __half g_alo[(size_t)NN * 256];
__device__ __half g_hhi[(size_t)NN * 256];
__device__ __half g_hlo[(size_t)NN * 256];
__device__ __half g_w0hi[256 * 256], g_w0lo[256 * 256];
__device__ __half g_w1hi[256 * 256], g_w1lo[256 * 256];
__device__ __half g_w2hi[64 * 256],  g_w2lo[64 * 256];
__device__ float g_as[NN * 4];
__device__ float g_ad[NN * 4];
__device__ int   g_cnt[NN];
__device__ int   g_incl[NBLK * SCAN_B];
__device__ int   g_bsum[NBLK];
__device__ int   g_rowptr[NN + 1];
__device__ int   g_fill[NN];
__device__ int   g_col[ET];

// ---------------- PTX helpers -----------------------------------------------------
__device__ __forceinline__ uint32_t smem_u32(const void* p) {
    uint32_t a;
    asm("{ .reg .u64 t; cvta.to.shared.u64 t, %1; cvt.u32.u64 %0, t; }" : "=r"(a) : "l"(p));
    return a;
}
__device__ __forceinline__ void cp_async16(uint32_t dst, const void* src) {
    asm volatile("cp.async.cg.shared.global [%0], [%1], 16;"
                 :: "r"(dst), "l"(__cvta_generic_to_global(src)) : "memory");
}
__device__ __forceinline__ void ldsm_x4(uint32_t& r0, uint32_t& r1, uint32_t& r2,
                                        uint32_t& r3, uint32_t addr) {
    asm volatile("ldmatrix.sync.aligned.m8n8.x4.shared.b16 {%0,%1,%2,%3}, [%4];"
                 : "=r"(r0), "=r"(r1), "=r"(r2), "=r"(r3) : "r"(addr));
}
__device__ __forceinline__ void mma16816(float* c, const uint32_t* a, const uint32_t* b) {
    asm volatile("mma.sync.aligned.m16n8k16.row.col.f32.f16.f16.f32 "
                 "{%0,%1,%2,%3}, {%4,%5,%6,%7}, {%8,%9}, {%0,%1,%2,%3};"
                 : "+f"(c[0]), "+f"(c[1]), "+f"(c[2]), "+f"(c[3])
                 : "r"(a[0]), "r"(a[1]), "r"(a[2]), "r"(a[3]), "r"(b[0]), "r"(b[1]));
}
#define SW128(o) ((o) ^ (((o) >> 3) & 0x70))

__device__ __forceinline__ void split2(float v, __half& hi, __half& lo) {
    hi = __float2half_rn(v);
    lo = __float2half_rn(v - __half2float(hi));
}

// ---------------- split conversions -----------------------------------------------
__global__ void k_split_x(const float* __restrict__ x) {
    int i = blockIdx.x * blockDim.x + threadIdx.x;
    if (i >= NN * 64) return;
    float4 v = ((const float4*)x)[i];
    __half h0, h1, h2, h3, l0, l1, l2, l3;
    split2(v.x, h0, l0); split2(v.y, h1, l1);
    split2(v.z, h2, l2); split2(v.w, h3, l3);
    ((__half2*)g_ahi)[2 * i]     = __halves2half2(h0, h1);
    ((__half2*)g_ahi)[2 * i + 1] = __halves2half2(h2, h3);
    ((__half2*)g_alo)[2 * i]     = __halves2half2(l0, l1);
    ((__half2*)g_alo)[2 * i + 1] = __halves2half2(l2, l3);
}

template <int NO>
__global__ void k_split_wt(const float* __restrict__ W, __half* __restrict__ hi,
                           __half* __restrict__ lo) {
    int i = blockIdx.x * blockDim.x + threadIdx.x;
    if (i >= 256 * NO) return;
    int k = i / NO, n = i % NO;
    __half h, l;
    split2(W[i], h, l);
    hi[n * 256 + k] = h;
    lo[n * 256 + k] = l;
}

// ---------------- GEMM: 4 warps, 64-wide warp tiles, 3-pass hi/lo fusion ----------
// k-block = 64: load Ahi/Alo/Bhi/Blo tiles once, run AhiBhi + AloBhi + AhiBlo.
// NO=256: fused per-head alpha epilogue; stores Hhi only.
// NO=64:  stores Hhi + Hlo (alpha done by k_alpha<1>).
template <int NO>
__global__ __launch_bounds__(128) void k_gemm_mma(const __half* __restrict__ Ahi,
                                                  const __half* __restrict__ Alo,
                                                  const __half* __restrict__ Bhi,
                                                  const __half* __restrict__ Blo,
                                                  __half* __restrict__ Hhi,
                                                  __half* __restrict__ Hlo,
                                                  const float* __restrict__ a_s,
                                                  const float* __restrict__ a_d) {
    constexpr int BM = 128, BN = (NO == 256) ? 128 : 64;
    constexpr int WN = BN / 2;            // 64 or 32
    constexpr int NG = WN / 8;            // 8 or 4
    constexpr int ASZ = 128 * 128;        // one A sub-tile (bytes)
    constexpr int BSZ = BN * 128;
    constexpr int STG = 2 * ASZ + 2 * BSZ;

    extern __shared__ __align__(1024) char smraw[];
    const uint32_t sb = smem_u32(smraw);
    const int tid = threadIdx.x, w = tid >> 5, lane = tid & 31;
    const int wm = w & 1, wn = w >> 1;    // 2x2 warp grid
    const int bm = blockIdx.y * BM, bn = blockIdx.x * BN;

    auto load = [&](int c) {
        const uint32_t st = sb + (c & 1) * STG;
        const int ko = c * 64;
        for (int t = tid; t < 128 * 8; t += 128) {
            int r = t >> 3, q = t & 7;
            int gr = bm + r; if (gr >= NN) gr = NN - 1;
            size_t go = (size_t)gr * 256 + ko + q * 8;
            uint32_t so = SW128(r * 128 + q * 16);
            cp_async16(st + so, Ahi + go);
            cp_async16(st + ASZ + so, Alo + go);
        }
        for (int t = tid; t < BN * 8; t += 128) {
            int r = t >> 3, q = t & 7;
            size_t go = (size_t)(bn + r) * 256 + ko + q * 8;
            uint32_t so = SW128(r * 128 + q * 16);
            cp_async16(st + 2 * ASZ + so, Bhi + go);
            cp_async16(st + 2 * ASZ + BSZ + so, Blo + go);
        }
        asm volatile("cp.async.commit_group;" ::: "memory");
    };

    load(0);
    load(1);

    float acc[4][NG][4] = {};
    const int a_row = wm * 64 + (lane & 15);
    const int a_colq = (lane >> 4) * 16;
    const int b_row = wn * WN + (lane >> 4) * 8 + (lane & 7);
    const int b_colq = ((lane >> 3) & 1) * 16;

    for (int c = 0; c < 4; ++c) {
        const uint32_t st = sb + (c & 1) * STG;
        if (c < 3) asm volatile("cp.async.wait_group 1;" ::: "memory");
        else       asm volatile("cp.async.wait_group 0;" ::: "memory");
        __syncthreads();
#pragma unroll
        for (int kk = 0; kk < 4; ++kk) {
            uint32_t ah[16], al[16], bb[2 * NG];
#pragma unroll
            for (int f = 0; f < 4; ++f)
                ldsm_x4(ah[f * 4], ah[f * 4 + 1], ah[f * 4 + 2], ah[f * 4 + 3],
                        st + SW128((a_row + f * 16) * 128 + kk * 32 + a_colq));
#pragma unroll
            for (int g2 = 0; g2 < NG / 2; ++g2)
                ldsm_x4(bb[g2 * 4], bb[g2 * 4 + 1], bb[g2 * 4 + 2], bb[g2 * 4 + 3],
                        st + 2 * ASZ + SW128((b_row + g2 * 16) * 128 + kk * 32 + b_colq));
#pragma unroll
            for (int f = 0; f < 4; ++f)
#pragma unroll
                for (int g = 0; g < NG; ++g)
                    mma16816(acc[f][g], ah + f * 4, bb + g * 2);
#pragma unroll
            for (int f = 0; f < 4; ++f)
                ldsm_x4(al[f * 4], al[f * 4 + 1], al[f * 4 + 2], al[f * 4 + 3],
                        st + ASZ + SW128((a_row + f * 16) * 128 + kk * 32 + a_colq));
#pragma unroll
            for (int f = 0; f < 4; ++f)
#pragma unroll
                for (int g = 0; g < NG; ++g)
                    mma16816(acc[f][g], al + f * 4, bb + g * 2);
#pragma unroll
            for (int g2 = 0; g2 < NG / 2; ++g2)
                ldsm_x4(bb[g2 * 4], bb[g2 * 4 + 1], bb[g2 * 4 + 2], bb[g2 * 4 + 3],
                        st + 2 * ASZ + BSZ + SW128((b_row + g2 * 16) * 128 + kk * 32 + b_colq));
#pragma unroll
            for (int f = 0; f < 4; ++f)
#pragma unroll
                for (int g = 0; g < NG; ++g)
                    mma16816(acc[f][g], ah + f * 4, bb + g * 2);
        }
        __syncthreads();
        if (c + 2 < 4) load(c + 2);
    }

    if constexpr (NO == 256) {
        // fused alpha: this warp's 64 cols = head (bx*2 + wn)
        const int head = blockIdx.x * 2 + wn;
        float as_r[2 * NG], ad_r[2 * NG];
#pragma unroll
        for (int g = 0; g < NG; ++g) {
            int cl = head * 64 + g * 8 + (lane & 3) * 2;
            as_r[g * 2] = a_s[cl];     as_r[g * 2 + 1] = a_s[cl + 1];
            ad_r[g * 2] = a_d[cl];     ad_r[g * 2 + 1] = a_d[cl + 1];
        }
#pragma unroll
        for (int f = 0; f < 4; ++f) {
#pragma unroll
            for (int rr = 0; rr < 2; ++rr) {
                float ps = 0.f, pd = 0.f;
#pragma unroll
                for (int g = 0; g < NG; ++g) {
                    float c0 = acc[f][g][rr * 2], c1 = acc[f][g][rr * 2 + 1];
                    ps += c0 * as_r[g * 2] + c1 * as_r[g * 2 + 1];
                    pd += c0 * ad_r[g * 2] + c1 * ad_r[g * 2 + 1];
                }
                ps += __shfl_xor_sync(0xffffffffu, ps, 1);
                ps += __shfl_xor_sync(0xffffffffu, ps, 2);
                pd += __shfl_xor_sync(0xffffffffu, pd, 1);
                pd += __shfl_xor_sync(0xffffffffu, pd, 2);
                int m = bm + wm * 64 + f * 16 + rr * 8 + (lane >> 2);
                if ((lane & 3) == 0 && m < NN) {
                    g_as[m * 4 + head] = ps;
                    g_ad[m * 4 + head] = pd;
                }
            }
        }
        // store hi only (conv messages use hi; alpha already computed exactly)
#pragma unroll
        for (int f = 0; f < 4; ++f) {
#pragma unroll
            for (int g = 0; g < NG; ++g) {
                int m = bm + wm * 64 + f * 16 + (lane >> 2);
                int n = bn + wn * 64 + g * 8 + (lane & 3) * 2;
#pragma unroll
                for (int rr = 0; rr < 2; ++rr) {
                    int mm = m + rr * 8;
                    if (mm < NN)
                        *(__half2*)(Hhi + (size_t)mm * NO + n) =
                            __floats2half2_rn(acc[f][g][rr * 2], acc[f][g][rr * 2 + 1]);
                }
            }
        }
    } else {
        // NO=64: store hi + lo (k_alpha<1> reconstructs fp32)
#pragma unroll
        for (int f = 0; f < 4; ++f) {
#pragma unroll
            for (int g = 0; g < NG; ++g) {
                int m = bm + wm * 64 + f * 16 + (lane >> 2);
                int n = bn + wn * WN + g * 8 + (lane & 3) * 2;
#pragma unroll
                for (int rr = 0; rr < 2; ++rr) {
                    int mm = m + rr * 8;
                    if (mm < NN) {
                        __half h0, h1, l0, l1;
                        split2(acc[f][g][rr * 2], h0, l0);
                        split2(acc[f][g][rr * 2 + 1], h1, l1);
                        *(__half2*)(Hhi + (size_t)mm * NO + n) = __halves2half2(h0, h1);
                        *(__half2*)(Hlo + (size_t)mm * NO + n) = __halves2half2(l0, l1);
                    }
                }
            }
        }
    }
}

// ---------------- CSR build -------------------------------------------------------
__global__ void k_zero_cnt() {
    int i = blockIdx.x * blockDim.x + threadIdx.x;
    if (i < NN) g_cnt[i] = 0;
}
__global__ void k_count(const int* __restrict__ ei) {
    int e = blockIdx.x * blockDim.x + threadIdx.x;
    if (e >= ET) return;
    int d = (e < EE) ? ei[EE + e] : (e - EE);
    atomicAdd(&g_cnt[d], 1);
}
__global__ void k_scan1() {
    __shared__ int sh[SCAN_B];
    int tid = threadIdx.x;
    int i = blockIdx.x * SCAN_B + tid;
    int v = (i < NN) ? g_cnt[i] : 0;
    sh[tid] = v;
    __syncthreads();
    for (int off = 1; off < SCAN_B; off <<= 1) {
        int t = (tid >= off) ? sh[tid - off] : 0;
        __syncthreads();
        sh[tid] += t;
        __syncthreads();
    }
    g_incl[i] = sh[tid];
    if (tid == SCAN_B - 1) g_bsum[blockIdx.x] = sh[tid];
}
__global__ void k_scan2() {
    if (threadIdx.x == 0) {
        int s = 0;
        for (int i = 0; i < NBLK; ++i) { int t = g_bsum[i]; g_bsum[i] = s; s += t; }
    }
}
__global__ void k_scan3() {
    int i = blockIdx.x * blockDim.x + threadIdx.x;
    if (i < NN) {
        int v = g_cnt[i];
        int ex = g_incl[i] - v + g_bsum[i >> 10];
        g_rowptr[i] = ex;
        g_fill[i] = ex;
    }
    if (i == 0) g_rowptr[NN] = ET;
}
__global__ void k_fill(const int* __restrict__ ei) {
    int e = blockIdx.x * blockDim.x + threadIdx.x;
    if (e >= ET) return;
    int s, d;
    if (e < EE) { s = ei[e]; d = ei[EE + e]; }
    else        { s = e - EE; d = s; }
    int pos = atomicAdd(&g_fill[d], 1);
    g_col[pos] = s;
}

// ---------------- alpha for last layer (H=1) --------------------------------------
__global__ __launch_bounds__(256) void k_alpha1(const float* __restrict__ a_s,
                                                const float* __restrict__ a_d,
                                                float* __restrict__ as_out,
                                                float* __restrict__ ad_out) {
    int warp = (blockIdx.x * blockDim.x + threadIdx.x) >> 5;
    int lane = threadIdx.x & 31;
    if (warp >= NN) return;
    const __half2* hr = (const __half2*)(g_hhi + (size_t)warp * 64);
    const __half2* lr = (const __half2*)(g_hlo + (size_t)warp * 64);
    float2 hf = __half22float2(hr[lane]);
    float2 lf = __half22float2(lr[lane]);
    float v0 = hf.x + lf.x, v1 = hf.y + lf.y;
    float ps = v0 * a_s[2 * lane] + v1 * a_s[2 * lane + 1];
    float pd = v0 * a_d[2 * lane] + v1 * a_d[2 * lane + 1];
#pragma unroll
    for (int o = 16; o; o >>= 1) {
        ps += __shfl_xor_sync(0xffffffffu, ps, o);
        pd += __shfl_xor_sync(0xffffffffu, pd, o);
    }
    if (lane == 0) { as_out[warp] = ps; ad_out[warp] = pd; }
}

// ---------------- GAT conv: online softmax + fp16 message gather ------------------
template <int HEADS, bool RELU, bool SPLIT>
__global__ __launch_bounds__(256) void k_conv(const float* __restrict__ as_,
                                              const float* __restrict__ ad_,
                                              const float* __restrict__ bias,
                                              float* __restrict__ out,
                                              __half* __restrict__ ohi,
                                              __half* __restrict__ olo) {
    const int TC = HEADS * 64;
    const int NPL = TC / 32;
    int warp = (blockIdx.x * blockDim.x + threadIdx.x) >> 5;
    int lane = threadIdx.x & 31;
    if (warp >= NN) return;
    int beg = g_rowptr[warp], end = g_rowptr[warp + 1];

    float adh[HEADS];
#pragma unroll
    for (int hh = 0; hh < HEADS; ++hh) adh[hh] = ad_[warp * HEADS + hh];

    float mx[HEADS], sm[HEADS];
#pragma unroll
    for (int hh = 0; hh < HEADS; ++hh) { mx[hh] = -1e30f; sm[hh] = 0.f; }
    for (int i = beg + lane; i < end; i += 32) {
        int s = g_col[i];
#pragma unroll
        for (int hh = 0; hh < HEADS; ++hh) {
            float e = as_[s * HEADS + hh] + adh[hh];
            e = e > 0.f ? e : 0.2f * e;
            if (e > mx[hh]) {
                sm[hh] = sm[hh] * __expf(mx[hh] - e) + 1.f;
                mx[hh] = e;
            } else {
                sm[hh] += __expf(e - mx[hh]);
            }
        }
    }
#pragma unroll
    for (int hh = 0; hh < HEADS; ++hh) {
#pragma unroll
        for (int o = 16; o; o >>= 1) {
            float mo = __shfl_xor_sync(0xffffffffu, mx[hh], o);
            float so = __shfl_xor_sync(0xffffffffu, sm[hh], o);
            float mn = fmaxf(mx[hh], mo);
            sm[hh] = sm[hh] * __expf(mx[hh] - mn) + so * __expf(mo - mn);
            mx[hh] = mn;
        }
    }

    const int myhead = (lane * NPL) / 64;
    float mm = mx[myhead], adm = adh[myhead], inv = 1.f / sm[myhead];
    float acc[NPL] = {};
    for (int i = beg; i < end; ++i) {
        int s = g_col[i];
        float e = as_[s * HEADS + myhead] + adm;
        e = e > 0.f ? e : 0.2f * e;
        float w = __expf(e - mm) * inv;
        const __half* hp = g_hhi + (size_t)s * TC + lane * NPL;
        if constexpr (NPL == 8) {
            uint4 raw = *(const uint4*)hp;
            float2 f0 = __half22float2(*(__half2*)&raw.x);
            float2 f1 = __half22float2(*(__half2*)&raw.y);
            float2 f2 = __half22float2(*(__half2*)&raw.z);
            float2 f3 = __half22float2(*(__half2*)&raw.w);
            acc[0] += w * f0.x; acc[1] += w * f0.y; acc[2] += w * f1.x; acc[3] += w * f1.y;
            acc[4] += w * f2.x; acc[5] += w * f2.y; acc[6] += w * f3.x; acc[7] += w * f3.y;
        } else {
            uint32_t raw = *(const uint32_t*)hp;
            float2 f0 = __half22float2(*(__half2*)&raw);
            acc[0] += w * f0.x; acc[1] += w * f0.y;
        }
    }
    float dinv = 1.f / (float)(end - beg);
    float v[NPL];
#pragma unroll
    for (int j = 0; j < NPL; ++j) {
        v[j] = acc[j] * dinv + bias[lane * NPL + j];
        if (RELU) v[j] = fmaxf(v[j], 0.f);
    }
    if constexpr (SPLIT) {
        __half2 vh[NPL / 2], vl[NPL / 2];
#pragma unroll
        for (int j = 0; j < NPL / 2; ++j) {
            __half h0, h1, l0, l1;
            split2(v[2 * j], h0, l0);
            split2(v[2 * j + 1], h1, l1);
            vh[j] = __halves2half2(h0, h1);
            vl[j] = __halves2half2(l0, l1);
        }
        size_t base = (size_t)warp * TC + lane * NPL;
        *(uint4*)(ohi + base) = *(uint4*)vh;
        *(uint4*)(olo + base) = *(uint4*)vl;
    } else {
#pragma unroll
        for (int j = 0; j < NPL; ++j)
            out[(size_t)warp * TC + lane * NPL + j] = v[j];
    }
}

// ---------------- launch ----------------------------------------------------------
extern "C" void kernel_launch(void* const* d_in, const int* in_sizes, int n_in,
                              void* d_out, int out_size) {
    const float* x   = (const float*)d_in[0];
    const int*   ei  = (const int*)d_in[1];
    const float* W0  = (const float*)d_in[2];
    const float* a0s = (const float*)d_in[3];
    const float* a0d = (const float*)d_in[4];
    const float* b0  = (const float*)d_in[5];
    const float* W1  = (const float*)d_in[6];
    const float* a1s = (const float*)d_in[7];
    const float* a1d = (const float*)d_in[8];
    const float* b1  = (const float*)d_in[9];
    const float* W2  = (const float*)d_in[10];
    const float* a2s = (const float*)d_in[11];
    const float* a2d = (const float*)d_in[12];
    const float* b2  = (const float*)d_in[13];
    float* out = (float*)d_out;

    void* p;
    cudaGetSymbolAddress(&p, g_ahi);  __half* ahi = (__half*)p;
    cudaGetSymbolAddress(&p, g_alo);  __half* alo = (__half*)p;
    cudaGetSymbolAddress(&p, g_hhi);  __half* hhi = (__half*)p;
    cudaGetSymbolAddress(&p, g_hlo);  __half* hlo = (__half*)p;
    cudaGetSymbolAddress(&p, g_w0hi); __half* w0hi = (__half*)p;
    cudaGetSymbolAddress(&p, g_w0lo); __half* w0lo = (__half*)p;
    cudaGetSymbolAddress(&p, g_w1hi); __half* w1hi = (__half*)p;
    cudaGetSymbolAddress(&p, g_w1lo); __half* w1lo = (__half*)p;
    cudaGetSymbolAddress(&p, g_w2hi); __half* w2hi = (__half*)p;
    cudaGetSymbolAddress(&p, g_w2lo); __half* w2lo = (__half*)p;
    cudaGetSymbolAddress(&p, g_as);   float* asb = (float*)p;
    cudaGetSymbolAddress(&p, g_ad);   float* adb = (float*)p;

    const int SMEM256 = 2 * (2 * 128 * 128 + 2 * 128 * 128);  // 131072
    const int SMEM64  = 2 * (2 * 128 * 128 + 2 * 64 * 128);   //  98304
    static bool attr_done = false;
    if (!attr_done) {
        cudaFuncSetAttribute(k_gemm_mma<256>, cudaFuncAttributeMaxDynamicSharedMemorySize, SMEM256);
        cudaFuncSetAttribute(k_gemm_mma<64>,  cudaFuncAttributeMaxDynamicSharedMemorySize, SMEM64);
        attr_done = true;
    }

    const int WPB = 8;
    const int NODE_BLKS = (NN + WPB - 1) / WPB;
    dim3 g256(2, (NN + 127) / 128);
    dim3 g64(1, (NN + 127) / 128);

    // launches 1-3; launch #4 (profiled) = layer-0 GEMM
    k_split_x<<<(NN * 64 + 255) / 256, 256>>>(x);
    k_split_wt<256><<<(256 * 256 + 255) / 256, 256>>>(W0, w0hi, w0lo);
    k_zero_cnt<<<(NN + 255) / 256, 256>>>();
    k_gemm_mma<256><<<g256, 128, SMEM256>>>(ahi, alo, w0hi, w0lo, hhi, nullptr, a0s, a0d);

    // CSR build
    k_count<<<(ET + 255) / 256, 256>>>(ei);
    k_scan1<<<NBLK, SCAN_B>>>();
    k_scan2<<<1, 32>>>();
    k_scan3<<<(NN + 255) / 256, 256>>>();
    k_fill<<<(ET + 255) / 256, 256>>>(ei);

    // layer 0 conv (alpha fused in GEMM epilogue)
    k_conv<4, true, true><<<NODE_BLKS, 256>>>(asb, adb, b0, nullptr, ahi, alo);

    // layer 1
    k_split_wt<256><<<(256 * 256 + 255) / 256, 256>>>(W1, w1hi, w1lo);
    k_gemm_mma<256><<<g256, 128, SMEM256>>>(ahi, alo, w1hi, w1lo, hhi, nullptr, a1s, a1d);
    k_conv<4, true, true><<<NODE_BLKS, 256>>>(asb, adb, b1, nullptr, ahi, alo);

    // layer 2 (heads=1)
    k_split_wt<64><<<(256 * 64 + 255) / 256, 256>>>(W2, w2hi, w2lo);
    k_gemm_mma<64><<<g64, 128, SMEM64>>>(ahi, alo, w2hi, w2lo, hhi, hlo, nullptr, nullptr);
    k_alpha1<<<NODE_BLKS, 256>>>(a2s, a2d, asb, adb);
    k_conv<1, false, false><<<NODE_BLKS, 256>>>(asb, adb, b2, out, nullptr, nullptr);
}

// round 6
// speedup vs baseline: 2.0239x; 1.0022x over previous
#include <cuda_runtime.h>
#include <cuda_fp16.h>
#include <cstdint>

#define NN 50000
#define EE 600000
#define ET (EE + NN)
#define SCAN_B 1024
#define NBLK ((NN + SCAN_B - 1) / SCAN_B)

// ---------------- scratch ---------------------------------------------------------
__device__ __half g_ahi[(size_t)NN * 256];
__device__ __half g_alo[(size_t)NN * 256];
__device__ __half g_hhi[(size_t)NN * 256];
__device__ __half g_hlo[(size_t)NN * 256];
__device__ __half g_w0hi[256 * 256], g_w0lo[256 * 256];
__device__ __half g_w1hi[256 * 256], g_w1lo[256 * 256];
__device__ __half g_w2hi[64 * 256],  g_w2lo[64 * 256];
__device__ float g_as[NN * 4];
__device__ float g_ad[NN * 4];
__device__ int   g_cnt[NN];
__device__ int   g_incl[NBLK * SCAN_B];
__device__ int   g_bsum[NBLK];
__device__ int   g_rowptr[NN + 1];
__device__ int   g_fill[NN];
__device__ int   g_col[ET];

// ---------------- PTX helpers -----------------------------------------------------
__device__ __forceinline__ uint32_t smem_u32(const void* p) {
    uint32_t a;
    asm("{ .reg .u64 t; cvta.to.shared.u64 t, %1; cvt.u32.u64 %0, t; }" : "=r"(a) : "l"(p));
    return a;
}
__device__ __forceinline__ void cp_async16(uint32_t dst, const void* src) {
    asm volatile("cp.async.cg.shared.global [%0], [%1], 16;"
                 :: "r"(dst), "l"(__cvta_generic_to_global(src)) : "memory");
}
__device__ __forceinline__ void ldsm_x4(uint32_t& r0, uint32_t& r1, uint32_t& r2,
                                        uint32_t& r3, uint32_t addr) {
    asm volatile("ldmatrix.sync.aligned.m8n8.x4.shared.b16 {%0,%1,%2,%3}, [%4];"
                 : "=r"(r0), "=r"(r1), "=r"(r2), "=r"(r3) : "r"(addr));
}
__device__ __forceinline__ void mma16816(float* c, const uint32_t* a, const uint32_t* b) {
    asm volatile("mma.sync.aligned.m16n8k16.row.col.f32.f16.f16.f32 "
                 "{%0,%1,%2,%3}, {%4,%5,%6,%7}, {%8,%9}, {%0,%1,%2,%3};"
                 : "+f"(c[0]), "+f"(c[1]), "+f"(c[2]), "+f"(c[3])
                 : "r"(a[0]), "r"(a[1]), "r"(a[2]), "r"(a[3]), "r"(b[0]), "r"(b[1]));
}
#define SW128(o) ((o) ^ (((o) >> 3) & 0x70))

__device__ __forceinline__ void split2(float v, __half& hi, __half& lo) {
    hi = __float2half_rn(v);
    lo = __float2half_rn(v - __half2float(hi));
}

// ---------------- split conversions -----------------------------------------------
__global__ void k_split_x(const float* __restrict__ x) {
    int i = blockIdx.x * blockDim.x + threadIdx.x;
    if (i >= NN * 64) return;
    float4 v = ((const float4*)x)[i];
    __half h0, h1, h2, h3, l0, l1, l2, l3;
    split2(v.x, h0, l0); split2(v.y, h1, l1);
    split2(v.z, h2, l2); split2(v.w, h3, l3);
    ((__half2*)g_ahi)[2 * i]     = __halves2half2(h0, h1);
    ((__half2*)g_ahi)[2 * i + 1] = __halves2half2(h2, h3);
    ((__half2*)g_alo)[2 * i]     = __halves2half2(l0, l1);
    ((__half2*)g_alo)[2 * i + 1] = __halves2half2(l2, l3);
}

template <int NO>
__global__ void k_split_wt(const float* __restrict__ W, __half* __restrict__ hi,
                           __half* __restrict__ lo) {
    int i = blockIdx.x * blockDim.x + threadIdx.x;
    if (i >= 256 * NO) return;
    int k = i / NO, n = i % NO;
    __half h, l;
    split2(W[i], h, l);
    hi[n * 256 + k] = h;
    lo[n * 256 + k] = l;
}

// ---------------- GEMM: 8 warps, warp tile 32xWN, 3-pass hi/lo fusion -------------
// Warp grid 4(m) x 2(n). NO=256: fused per-head alpha epilogue; stores Hhi only.
template <int NO>
__global__ __launch_bounds__(256) void k_gemm_mma(const __half* __restrict__ Ahi,
                                                  const __half* __restrict__ Alo,
                                                  const __half* __restrict__ Bhi,
                                                  const __half* __restrict__ Blo,
                                                  __half* __restrict__ Hhi,
                                                  __half* __restrict__ Hlo,
                                                  const float* __restrict__ a_s,
                                                  const float* __restrict__ a_d) {
    constexpr int BM = 128, BN = (NO == 256) ? 128 : 64;
    constexpr int WN = BN / 2;            // 64 or 32
    constexpr int NG = WN / 8;            // 8 or 4
    constexpr int ASZ = 128 * 128;        // A sub-tile bytes (128 rows x 128B)
    constexpr int BSZ = BN * 128;
    constexpr int STG = 2 * ASZ + 2 * BSZ;

    extern __shared__ __align__(1024) char smraw[];
    const uint32_t sb = smem_u32(smraw);
    const int tid = threadIdx.x, w = tid >> 5, lane = tid & 31;
    const int wm = w & 3, wn = w >> 2;    // 4x2 warp grid
    const int bm = blockIdx.y * BM, bn = blockIdx.x * BN;

    auto load = [&](int c) {
        const uint32_t st = sb + (c & 1) * STG;
        const int ko = c * 64;
        for (int t = tid; t < 128 * 8; t += 256) {
            int r = t >> 3, q = t & 7;
            int gr = bm + r; if (gr >= NN) gr = NN - 1;
            size_t go = (size_t)gr * 256 + ko + q * 8;
            uint32_t so = SW128(r * 128 + q * 16);
            cp_async16(st + so, Ahi + go);
            cp_async16(st + ASZ + so, Alo + go);
        }
        for (int t = tid; t < BN * 8; t += 256) {
            int r = t >> 3, q = t & 7;
            size_t go = (size_t)(bn + r) * 256 + ko + q * 8;
            uint32_t so = SW128(r * 128 + q * 16);
            cp_async16(st + 2 * ASZ + so, Bhi + go);
            cp_async16(st + 2 * ASZ + BSZ + so, Blo + go);
        }
        asm volatile("cp.async.commit_group;" ::: "memory");
    };

    load(0);
    load(1);

    float acc[2][NG][4] = {};
    const int a_row = wm * 32 + (lane & 15);
    const int a_colq = (lane >> 4) * 16;
    const int b_row = wn * WN + (lane >> 4) * 8 + (lane & 7);
    const int b_colq = ((lane >> 3) & 1) * 16;

    for (int c = 0; c < 4; ++c) {
        const uint32_t st = sb + (c & 1) * STG;
        if (c < 3) asm volatile("cp.async.wait_group 1;" ::: "memory");
        else       asm volatile("cp.async.wait_group 0;" ::: "memory");
        __syncthreads();
#pragma unroll
        for (int kk = 0; kk < 4; ++kk) {
            uint32_t ah[8], al[8], bb[2 * NG];
#pragma unroll
            for (int f = 0; f < 2; ++f)
                ldsm_x4(ah[f * 4], ah[f * 4 + 1], ah[f * 4 + 2], ah[f * 4 + 3],
                        st + SW128((a_row + f * 16) * 128 + kk * 32 + a_colq));
#pragma unroll
            for (int g2 = 0; g2 < NG / 2; ++g2)
                ldsm_x4(bb[g2 * 4], bb[g2 * 4 + 1], bb[g2 * 4 + 2], bb[g2 * 4 + 3],
                        st + 2 * ASZ + SW128((b_row + g2 * 16) * 128 + kk * 32 + b_colq));
#pragma unroll
            for (int f = 0; f < 2; ++f)
#pragma unroll
                for (int g = 0; g < NG; ++g)
                    mma16816(acc[f][g], ah + f * 4, bb + g * 2);
#pragma unroll
            for (int f = 0; f < 2; ++f)
                ldsm_x4(al[f * 4], al[f * 4 + 1], al[f * 4 + 2], al[f * 4 + 3],
                        st + ASZ + SW128((a_row + f * 16) * 128 + kk * 32 + a_colq));
#pragma unroll
            for (int f = 0; f < 2; ++f)
#pragma unroll
                for (int g = 0; g < NG; ++g)
                    mma16816(acc[f][g], al + f * 4, bb + g * 2);
#pragma unroll
            for (int g2 = 0; g2 < NG / 2; ++g2)
                ldsm_x4(bb[g2 * 4], bb[g2 * 4 + 1], bb[g2 * 4 + 2], bb[g2 * 4 + 3],
                        st + 2 * ASZ + BSZ + SW128((b_row + g2 * 16) * 128 + kk * 32 + b_colq));
#pragma unroll
            for (int f = 0; f < 2; ++f)
#pragma unroll
                for (int g = 0; g < NG; ++g)
                    mma16816(acc[f][g], ah + f * 4, bb + g * 2);
        }
        __syncthreads();
        if (c + 2 < 4) load(c + 2);
    }

    if constexpr (NO == 256) {
        // fused alpha: warp's 64 cols = head (bx*2 + wn)
        const int head = blockIdx.x * 2 + wn;
        float as_r[2 * NG], ad_r[2 * NG];
#pragma unroll
        for (int g = 0; g < NG; ++g) {
            int cl = head * 64 + g * 8 + (lane & 3) * 2;
            as_r[g * 2] = a_s[cl];     as_r[g * 2 + 1] = a_s[cl + 1];
            ad_r[g * 2] = a_d[cl];     ad_r[g * 2 + 1] = a_d[cl + 1];
        }
#pragma unroll
        for (int f = 0; f < 2; ++f) {
#pragma unroll
            for (int rr = 0; rr < 2; ++rr) {
                float ps = 0.f, pd = 0.f;
#pragma unroll
                for (int g = 0; g < NG; ++g) {
                    float c0 = acc[f][g][rr * 2], c1 = acc[f][g][rr * 2 + 1];
                    ps += c0 * as_r[g * 2] + c1 * as_r[g * 2 + 1];
                    pd += c0 * ad_r[g * 2] + c1 * ad_r[g * 2 + 1];
                }
                ps += __shfl_xor_sync(0xffffffffu, ps, 1);
                ps += __shfl_xor_sync(0xffffffffu, ps, 2);
                pd += __shfl_xor_sync(0xffffffffu, pd, 1);
                pd += __shfl_xor_sync(0xffffffffu, pd, 2);
                int m = bm + wm * 32 + f * 16 + rr * 8 + (lane >> 2);
                if ((lane & 3) == 0 && m < NN) {
                    g_as[m * 4 + head] = ps;
                    g_ad[m * 4 + head] = pd;
                }
            }
        }
#pragma unroll
        for (int f = 0; f < 2; ++f) {
#pragma unroll
            for (int g = 0; g < NG; ++g) {
                int m = bm + wm * 32 + f * 16 + (lane >> 2);
                int n = bn + wn * 64 + g * 8 + (lane & 3) * 2;
#pragma unroll
                for (int rr = 0; rr < 2; ++rr) {
                    int mm = m + rr * 8;
                    if (mm < NN)
                        *(__half2*)(Hhi + (size_t)mm * NO + n) =
                            __floats2half2_rn(acc[f][g][rr * 2], acc[f][g][rr * 2 + 1]);
                }
            }
        }
    } else {
#pragma unroll
        for (int f = 0; f < 2; ++f) {
#pragma unroll
            for (int g = 0; g < NG; ++g) {
                int m = bm + wm * 32 + f * 16 + (lane >> 2);
                int n = bn + wn * WN + g * 8 + (lane & 3) * 2;
#pragma unroll
                for (int rr = 0; rr < 2; ++rr) {
                    int mm = m + rr * 8;
                    if (mm < NN) {
                        __half h0, h1, l0, l1;
                        split2(acc[f][g][rr * 2], h0, l0);
                        split2(acc[f][g][rr * 2 + 1], h1, l1);
                        *(__half2*)(Hhi + (size_t)mm * NO + n) = __halves2half2(h0, h1);
                        *(__half2*)(Hlo + (size_t)mm * NO + n) = __halves2half2(l0, l1);
                    }
                }
            }
        }
    }
}

// ---------------- CSR build -------------------------------------------------------
__global__ void k_zero_cnt() {
    int i = blockIdx.x * blockDim.x + threadIdx.x;
    if (i < NN) g_cnt[i] = 0;
}
__global__ void k_count(const int* __restrict__ ei) {
    int e = blockIdx.x * blockDim.x + threadIdx.x;
    if (e >= ET) return;
    int d = (e < EE) ? ei[EE + e] : (e - EE);
    atomicAdd(&g_cnt[d], 1);
}
__global__ void k_scan1() {
    __shared__ int sh[SCAN_B];
    int tid = threadIdx.x;
    int i = blockIdx.x * SCAN_B + tid;
    int v = (i < NN) ? g_cnt[i] : 0;
    sh[tid] = v;
    __syncthreads();
    for (int off = 1; off < SCAN_B; off <<= 1) {
        int t = (tid >= off) ? sh[tid - off] : 0;
        __syncthreads();
        sh[tid] += t;
        __syncthreads();
    }
    g_incl[i] = sh[tid];
    if (tid == SCAN_B - 1) g_bsum[blockIdx.x] = sh[tid];
}
__global__ void k_scan2() {
    if (threadIdx.x == 0) {
        int s = 0;
        for (int i = 0; i < NBLK; ++i) { int t = g_bsum[i]; g_bsum[i] = s; s += t; }
    }
}
__global__ void k_scan3() {
    int i = blockIdx.x * blockDim.x + threadIdx.x;
    if (i < NN) {
        int v = g_cnt[i];
        int ex = g_incl[i] - v + g_bsum[i >> 10];
        g_rowptr[i] = ex;
        g_fill[i] = ex;
    }
    if (i == 0) g_rowptr[NN] = ET;
}
__global__ void k_fill(const int* __restrict__ ei) {
    int e = blockIdx.x * blockDim.x + threadIdx.x;
    if (e >= ET) return;
    int s, d;
    if (e < EE) { s = ei[e]; d = ei[EE + e]; }
    else        { s = e - EE; d = s; }
    int pos = atomicAdd(&g_fill[d], 1);
    g_col[pos] = s;
}

// ---------------- alpha for last layer (H=1) --------------------------------------
__global__ __launch_bounds__(256) void k_alpha1(const float* __restrict__ a_s,
                                                const float* __restrict__ a_d,
                                                float* __restrict__ as_out,
                                                float* __restrict__ ad_out) {
    int warp = (blockIdx.x * blockDim.x + threadIdx.x) >> 5;
    int lane = threadIdx.x & 31;
    if (warp >= NN) return;
    const __half2* hr = (const __half2*)(g_hhi + (size_t)warp * 64);
    const __half2* lr = (const __half2*)(g_hlo + (size_t)warp * 64);
    float2 hf = __half22float2(hr[lane]);
    float2 lf = __half22float2(lr[lane]);
    float v0 = hf.x + lf.x, v1 = hf.y + lf.y;
    float ps = v0 * a_s[2 * lane] + v1 * a_s[2 * lane + 1];
    float pd = v0 * a_d[2 * lane] + v1 * a_d[2 * lane + 1];
#pragma unroll
    for (int o = 16; o; o >>= 1) {
        ps += __shfl_xor_sync(0xffffffffu, ps, o);
        pd += __shfl_xor_sync(0xffffffffu, pd, o);
    }
    if (lane == 0) { as_out[warp] = ps; ad_out[warp] = pd; }
}

// ---------------- GAT conv: online softmax + fp16 message gather ------------------
template <int HEADS, bool RELU, bool SPLIT>
__global__ __launch_bounds__(256) void k_conv(const float* __restrict__ as_,
                                              const float* __restrict__ ad_,
                                              const float* __restrict__ bias,
                                              float* __restrict__ out,
                                              __half* __restrict__ ohi,
                                              __half* __restrict__ olo) {
    const int TC = HEADS * 64;
    const int NPL = TC / 32;
    int warp = (blockIdx.x * blockDim.x + threadIdx.x) >> 5;
    int lane = threadIdx.x & 31;
    if (warp >= NN) return;
    int beg = g_rowptr[warp], end = g_rowptr[warp + 1];

    float adh[HEADS];
#pragma unroll
    for (int hh = 0; hh < HEADS; ++hh) adh[hh] = ad_[warp * HEADS + hh];

    float mx[HEADS], sm[HEADS];
#pragma unroll
    for (int hh = 0; hh < HEADS; ++hh) { mx[hh] = -1e30f; sm[hh] = 0.f; }
    for (int i = beg + lane; i < end; i += 32) {
        int s = g_col[i];
#pragma unroll
        for (int hh = 0; hh < HEADS; ++hh) {
            float e = as_[s * HEADS + hh] + adh[hh];
            e = e > 0.f ? e : 0.2f * e;
            if (e > mx[hh]) {
                sm[hh] = sm[hh] * __expf(mx[hh] - e) + 1.f;
                mx[hh] = e;
            } else {
                sm[hh] += __expf(e - mx[hh]);
            }
        }
    }
#pragma unroll
    for (int hh = 0; hh < HEADS; ++hh) {
#pragma unroll
        for (int o = 16; o; o >>= 1) {
            float mo = __shfl_xor_sync(0xffffffffu, mx[hh], o);
            float so = __shfl_xor_sync(0xffffffffu, sm[hh], o);
            float mn = fmaxf(mx[hh], mo);
            sm[hh] = sm[hh] * __expf(mx[hh] - mn) + so * __expf(mo - mn);
            mx[hh] = mn;
        }
    }

    const int myhead = (lane * NPL) / 64;
    float mm = mx[myhead], adm = adh[myhead], inv = 1.f / sm[myhead];
    float acc[NPL] = {};
    for (int i = beg; i < end; ++i) {
        int s = g_col[i];
        float e = as_[s * HEADS + myhead] + adm;
        e = e > 0.f ? e : 0.2f * e;
        float w = __expf(e - mm) * inv;
        const __half* hp = g_hhi + (size_t)s * TC + lane * NPL;
        if constexpr (NPL == 8) {
            uint4 raw = *(const uint4*)hp;
            float2 f0 = __half22float2(*(__half2*)&raw.x);
            float2 f1 = __half22float2(*(__half2*)&raw.y);
            float2 f2 = __half22float2(*(__half2*)&raw.z);
            float2 f3 = __half22float2(*(__half2*)&raw.w);
            acc[0] += w * f0.x; acc[1] += w * f0.y; acc[2] += w * f1.x; acc[3] += w * f1.y;
            acc[4] += w * f2.x; acc[5] += w * f2.y; acc[6] += w * f3.x; acc[7] += w * f3.y;
        } else {
            uint32_t raw = *(const uint32_t*)hp;
            float2 f0 = __half22float2(*(__half2*)&raw);
            acc[0] += w * f0.x; acc[1] += w * f0.y;
        }
    }
    float dinv = 1.f / (float)(end - beg);
    float v[NPL];
#pragma unroll
    for (int j = 0; j < NPL; ++j) {
        v[j] = acc[j] * dinv + bias[lane * NPL + j];
        if (RELU) v[j] = fmaxf(v[j], 0.f);
    }
    if constexpr (SPLIT) {
        __half2 vh[NPL / 2], vl[NPL / 2];
#pragma unroll
        for (int j = 0; j < NPL / 2; ++j) {
            __half h0, h1, l0, l1;
            split2(v[2 * j], h0, l0);
            split2(v[2 * j + 1], h1, l1);
            vh[j] = __halves2half2(h0, h1);
            vl[j] = __halves2half2(l0, l1);
        }
        size_t base = (size_t)warp * TC + lane * NPL;
        *(uint4*)(ohi + base) = *(uint4*)vh;
        *(uint4*)(olo + base) = *(uint4*)vl;
    } else {
#pragma unroll
        for (int j = 0; j < NPL; ++j)
            out[(size_t)warp * TC + lane * NPL + j] = v[j];
    }
}

// ---------------- launch ----------------------------------------------------------
extern "C" void kernel_launch(void* const* d_in, const int* in_sizes, int n_in,
                              void* d_out, int out_size) {
    const float* x   = (const float*)d_in[0];
    const int*   ei  = (const int*)d_in[1];
    const float* W0  = (const float*)d_in[2];
    const float* a0s = (const float*)d_in[3];
    const float* a0d = (const float*)d_in[4];
    const float* b0  = (const float*)d_in[5];
    const float* W1  = (const float*)d_in[6];
    const float* a1s = (const float*)d_in[7];
    const float* a1d = (const float*)d_in[8];
    const float* b1  = (const float*)d_in[9];
    const float* W2  = (const float*)d_in[10];
    const float* a2s = (const float*)d_in[11];
    const float* a2d = (const float*)d_in[12];
    const float* b2  = (const float*)d_in[13];
    float* out = (float*)d_out;

    void* p;
    cudaGetSymbolAddress(&p, g_ahi);  __half* ahi = (__half*)p;
    cudaGetSymbolAddress(&p, g_alo);  __half* alo = (__half*)p;
    cudaGetSymbolAddress(&p, g_hhi);  __half* hhi = (__half*)p;
    cudaGetSymbolAddress(&p, g_hlo);  __half* hlo = (__half*)p;
    cudaGetSymbolAddress(&p, g_w0hi); __half* w0hi = (__half*)p;
    cudaGetSymbolAddress(&p, g_w0lo); __half* w0lo = (__half*)p;
    cudaGetSymbolAddress(&p, g_w1hi); __half* w1hi = (__half*)p;
    cudaGetSymbolAddress(&p, g_w1lo); __half* w1lo = (__half*)p;
    cudaGetSymbolAddress(&p, g_w2hi); __half* w2hi = (__half*)p;
    cudaGetSymbolAddress(&p, g_w2lo); __half* w2lo = (__half*)p;
    cudaGetSymbolAddress(&p, g_as);   float* asb = (float*)p;
    cudaGetSymbolAddress(&p, g_ad);   float* adb = (float*)p;

    const int SMEM256 = 2 * (2 * 128 * 128 + 2 * 128 * 128);  // 131072
    const int SMEM64  = 2 * (2 * 128 * 128 + 2 * 64 * 128);   //  98304
    static bool attr_done = false;
    if (!attr_done) {
        cudaFuncSetAttribute(k_gemm_mma<256>, cudaFuncAttributeMaxDynamicSharedMemorySize, SMEM256);
        cudaFuncSetAttribute(k_gemm_mma<64>,  cudaFuncAttributeMaxDynamicSharedMemorySize, SMEM64);
        attr_done = true;
    }

    const int WPB = 8;
    const int NODE_BLKS = (NN + WPB - 1) / WPB;
    dim3 g256(2, (NN + 127) / 128);
    dim3 g64(1, (NN + 127) / 128);

    // launches 1-3; launch #4 (profiled) = layer-0 GEMM
    k_split_x<<<(NN * 64 + 255) / 256, 256>>>(x);
    k_split_wt<256><<<(256 * 256 + 255) / 256, 256>>>(W0, w0hi, w0lo);
    k_zero_cnt<<<(NN + 255) / 256, 256>>>();
    k_gemm_mma<256><<<g256, 256, SMEM256>>>(ahi, alo, w0hi, w0lo, hhi, nullptr, a0s, a0d);

    // CSR build
    k_count<<<(ET + 255) / 256, 256>>>(ei);
    k_scan1<<<NBLK, SCAN_B>>>();
    k_scan2<<<1, 32>>>();
    k_scan3<<<(NN + 255) / 256, 256>>>();
    k_fill<<<(ET + 255) / 256, 256>>>(ei);

    // layer 0 conv (alpha fused in GEMM epilogue)
    k_conv<4, true, true><<<NODE_BLKS, 256>>>(asb, adb, b0, nullptr, ahi, alo);

    // layer 1
    k_split_wt<256><<<(256 * 256 + 255) / 256, 256>>>(W1, w1hi, w1lo);
    k_gemm_mma<256><<<g256, 256, SMEM256>>>(ahi, alo, w1hi, w1lo, hhi, nullptr, a1s, a1d);
    k_conv<4, true, true><<<NODE_BLKS, 256>>>(asb, adb, b1, nullptr, ahi, alo);

    // layer 2 (heads=1)
    k_split_wt<64><<<(256 * 64 + 255) / 256, 256>>>(W2, w2hi, w2lo);
    k_gemm_mma<64><<<g64, 256, SMEM64>>>(ahi, alo, w2hi, w2lo, hhi, hlo, nullptr, nullptr);
    k_alpha1<<<NODE_BLKS, 256>>>(a2s, a2d, asb, adb);
    k_conv<1, false, false><<<NODE_BLKS, 256>>>(asb, adb, b2, out, nullptr, nullptr);
}

// round 7
// speedup vs baseline: 2.3869x; 1.1794x over previous
#include <cuda_runtime.h>
#include <cuda_fp16.h>
#include <cstdint>

#define NN 50000
#define EE 600000
#define ET (EE + NN)
#define SCAN_B 1024
#define NBLK ((NN + SCAN_B - 1) / SCAN_B)

// ---------------- scratch ---------------------------------------------------------
__device__ __half g_ahi[(size_t)NN * 256];      // layer input, fp16
__device__ __half g_hhi[(size_t)NN * 256];      // GEMM output hi
__device__ __half g_hlo[(size_t)NN * 256];      // GEMM output lo (layer 2 only)
__device__ __half g_w0hi[256 * 256], g_w0lo[256 * 256];
__device__ __half g_w1hi[256 * 256], g_w1lo[256 * 256];
__device__ __half g_w2hi[64 * 256],  g_w2lo[64 * 256];
__device__ float g_as[NN * 4];
__device__ float g_ad[NN * 4];
__device__ int   g_cnt[NN];
__device__ int   g_incl[NBLK * SCAN_B];
__device__ int   g_bsum[NBLK];
__device__ int   g_rowptr[NN + 1];
__device__ int   g_fill[NN];
__device__ int   g_col[ET];

// ---------------- PTX helpers -----------------------------------------------------
__device__ __forceinline__ uint32_t smem_u32(const void* p) {
    uint32_t a;
    asm("{ .reg .u64 t; cvta.to.shared.u64 t, %1; cvt.u32.u64 %0, t; }" : "=r"(a) : "l"(p));
    return a;
}
__device__ __forceinline__ void cp_async16(uint32_t dst, const void* src) {
    asm volatile("cp.async.cg.shared.global [%0], [%1], 16;"
                 :: "r"(dst), "l"(__cvta_generic_to_global(src)) : "memory");
}
__device__ __forceinline__ void ldsm_x4(uint32_t& r0, uint32_t& r1, uint32_t& r2,
                                        uint32_t& r3, uint32_t addr) {
    asm volatile("ldmatrix.sync.aligned.m8n8.x4.shared.b16 {%0,%1,%2,%3}, [%4];"
                 : "=r"(r0), "=r"(r1), "=r"(r2), "=r"(r3) : "r"(addr));
}
__device__ __forceinline__ void mma16816(float* c, const uint32_t* a, const uint32_t* b) {
    asm volatile("mma.sync.aligned.m16n8k16.row.col.f32.f16.f16.f32 "
                 "{%0,%1,%2,%3}, {%4,%5,%6,%7}, {%8,%9}, {%0,%1,%2,%3};"
                 : "+f"(c[0]), "+f"(c[1]), "+f"(c[2]), "+f"(c[3])
                 : "r"(a[0]), "r"(a[1]), "r"(a[2]), "r"(a[3]), "r"(b[0]), "r"(b[1]));
}
#define SW128(o) ((o) ^ (((o) >> 3) & 0x70))

__device__ __forceinline__ void split2(float v, __half& hi, __half& lo) {
    hi = __float2half_rn(v);
    lo = __float2half_rn(v - __half2float(hi));
}

// ---------------- conversions -----------------------------------------------------
__global__ void k_tofp16_x(const float* __restrict__ x) {
    int i = blockIdx.x * blockDim.x + threadIdx.x;
    if (i >= NN * 64) return;
    float4 v = ((const float4*)x)[i];
    ((__half2*)g_ahi)[2 * i]     = __floats2half2_rn(v.x, v.y);
    ((__half2*)g_ahi)[2 * i + 1] = __floats2half2_rn(v.z, v.w);
}

template <int NO>
__global__ void k_split_wt(const float* __restrict__ W, __half* __restrict__ hi,
                           __half* __restrict__ lo) {
    int i = blockIdx.x * blockDim.x + threadIdx.x;
    if (i >= 256 * NO) return;
    int k = i / NO, n = i % NO;
    __half h, l;
    split2(W[i], h, l);
    hi[n * 256 + k] = h;
    lo[n * 256 + k] = l;
}

// ---------------- GEMM: 8 warps, A fp16, B hi/lo (2 passes), fused alpha ----------
template <int NO>
__global__ __launch_bounds__(256, 2) void k_gemm_mma(const __half* __restrict__ A,
                                                     const __half* __restrict__ Bhi,
                                                     const __half* __restrict__ Blo,
                                                     __half* __restrict__ Hhi,
                                                     __half* __restrict__ Hlo,
                                                     const float* __restrict__ a_s,
                                                     const float* __restrict__ a_d) {
    constexpr int BM = 128, BN = (NO == 256) ? 128 : 64;
    constexpr int WN = BN / 2;            // 64 or 32
    constexpr int NG = WN / 8;            // 8 or 4
    constexpr int ASZ = 128 * 128;        // A tile bytes (128 rows x 128B)
    constexpr int BSZ = BN * 128;
    constexpr int STG = ASZ + 2 * BSZ;

    extern __shared__ __align__(1024) char smraw[];
    const uint32_t sb = smem_u32(smraw);
    const int tid = threadIdx.x, w = tid >> 5, lane = tid & 31;
    const int wm = w & 3, wn = w >> 2;    // 4x2 warp grid
    const int bm = blockIdx.y * BM, bn = blockIdx.x * BN;

    auto load = [&](int c) {
        const uint32_t st = sb + (c & 1) * STG;
        const int ko = c * 64;
        for (int t = tid; t < 128 * 8; t += 256) {
            int r = t >> 3, q = t & 7;
            int gr = bm + r; if (gr >= NN) gr = NN - 1;
            cp_async16(st + SW128(r * 128 + q * 16), A + (size_t)gr * 256 + ko + q * 8);
        }
        for (int t = tid; t < BN * 8; t += 256) {
            int r = t >> 3, q = t & 7;
            size_t go = (size_t)(bn + r) * 256 + ko + q * 8;
            uint32_t so = SW128(r * 128 + q * 16);
            cp_async16(st + ASZ + so, Bhi + go);
            cp_async16(st + ASZ + BSZ + so, Blo + go);
        }
        asm volatile("cp.async.commit_group;" ::: "memory");
    };

    load(0);
    load(1);

    float acc[2][NG][4] = {};
    const int a_row = wm * 32 + (lane & 15);
    const int a_colq = (lane >> 4) * 16;
    const int b_row = wn * WN + (lane >> 4) * 8 + (lane & 7);
    const int b_colq = ((lane >> 3) & 1) * 16;

    for (int c = 0; c < 4; ++c) {
        const uint32_t st = sb + (c & 1) * STG;
        if (c < 3) asm volatile("cp.async.wait_group 1;" ::: "memory");
        else       asm volatile("cp.async.wait_group 0;" ::: "memory");
        __syncthreads();
#pragma unroll
        for (int kk = 0; kk < 4; ++kk) {
            uint32_t ah[8], bb[2 * NG];
#pragma unroll
            for (int f = 0; f < 2; ++f)
                ldsm_x4(ah[f * 4], ah[f * 4 + 1], ah[f * 4 + 2], ah[f * 4 + 3],
                        st + SW128((a_row + f * 16) * 128 + kk * 32 + a_colq));
#pragma unroll
            for (int g2 = 0; g2 < NG / 2; ++g2)
                ldsm_x4(bb[g2 * 4], bb[g2 * 4 + 1], bb[g2 * 4 + 2], bb[g2 * 4 + 3],
                        st + ASZ + SW128((b_row + g2 * 16) * 128 + kk * 32 + b_colq));
#pragma unroll
            for (int f = 0; f < 2; ++f)
#pragma unroll
                for (int g = 0; g < NG; ++g)
                    mma16816(acc[f][g], ah + f * 4, bb + g * 2);
#pragma unroll
            for (int g2 = 0; g2 < NG / 2; ++g2)
                ldsm_x4(bb[g2 * 4], bb[g2 * 4 + 1], bb[g2 * 4 + 2], bb[g2 * 4 + 3],
                        st + ASZ + BSZ + SW128((b_row + g2 * 16) * 128 + kk * 32 + b_colq));
#pragma unroll
            for (int f = 0; f < 2; ++f)
#pragma unroll
                for (int g = 0; g < NG; ++g)
                    mma16816(acc[f][g], ah + f * 4, bb + g * 2);
        }
        __syncthreads();
        if (c + 2 < 4) load(c + 2);
    }

    if constexpr (NO == 256) {
        // fused alpha: warp's 64 cols = head (bx*2 + wn)
        const int head = blockIdx.x * 2 + wn;
        float as_r[2 * NG], ad_r[2 * NG];
#pragma unroll
        for (int g = 0; g < NG; ++g) {
            int cl = head * 64 + g * 8 + (lane & 3) * 2;
            as_r[g * 2] = a_s[cl];     as_r[g * 2 + 1] = a_s[cl + 1];
            ad_r[g * 2] = a_d[cl];     ad_r[g * 2 + 1] = a_d[cl + 1];
        }
#pragma unroll
        for (int f = 0; f < 2; ++f) {
#pragma unroll
            for (int rr = 0; rr < 2; ++rr) {
                float ps = 0.f, pd = 0.f;
#pragma unroll
                for (int g = 0; g < NG; ++g) {
                    float c0 = acc[f][g][rr * 2], c1 = acc[f][g][rr * 2 + 1];
                    ps += c0 * as_r[g * 2] + c1 * as_r[g * 2 + 1];
                    pd += c0 * ad_r[g * 2] + c1 * ad_r[g * 2 + 1];
                }
                ps += __shfl_xor_sync(0xffffffffu, ps, 1);
                ps += __shfl_xor_sync(0xffffffffu, ps, 2);
                pd += __shfl_xor_sync(0xffffffffu, pd, 1);
                pd += __shfl_xor_sync(0xffffffffu, pd, 2);
                int m = bm + wm * 32 + f * 16 + rr * 8 + (lane >> 2);
                if ((lane & 3) == 0 && m < NN) {
                    g_as[m * 4 + head] = ps;
                    g_ad[m * 4 + head] = pd;
                }
            }
        }
#pragma unroll
        for (int f = 0; f < 2; ++f) {
#pragma unroll
            for (int g = 0; g < NG; ++g) {
                int m = bm + wm * 32 + f * 16 + (lane >> 2);
                int n = bn + wn * 64 + g * 8 + (lane & 3) * 2;
#pragma unroll
                for (int rr = 0; rr < 2; ++rr) {
                    int mm = m + rr * 8;
                    if (mm < NN)
                        *(__half2*)(Hhi + (size_t)mm * NO + n) =
                            __floats2half2_rn(acc[f][g][rr * 2], acc[f][g][rr * 2 + 1]);
                }
            }
        }
    } else {
#pragma unroll
        for (int f = 0; f < 2; ++f) {
#pragma unroll
            for (int g = 0; g < NG; ++g) {
                int m = bm + wm * 32 + f * 16 + (lane >> 2);
                int n = bn + wn * WN + g * 8 + (lane & 3) * 2;
#pragma unroll
                for (int rr = 0; rr < 2; ++rr) {
                    int mm = m + rr * 8;
                    if (mm < NN) {
                        __half h0, h1, l0, l1;
                        split2(acc[f][g][rr * 2], h0, l0);
                        split2(acc[f][g][rr * 2 + 1], h1, l1);
                        *(__half2*)(Hhi + (size_t)mm * NO + n) = __halves2half2(h0, h1);
                        *(__half2*)(Hlo + (size_t)mm * NO + n) = __halves2half2(l0, l1);
                    }
                }
            }
        }
    }
}

// ---------------- CSR build -------------------------------------------------------
__global__ void k_zero_cnt() {
    int i = blockIdx.x * blockDim.x + threadIdx.x;
    if (i < NN) g_cnt[i] = 0;
}
__global__ void k_count(const int* __restrict__ ei) {
    int e = blockIdx.x * blockDim.x + threadIdx.x;
    if (e >= ET) return;
    int d = (e < EE) ? ei[EE + e] : (e - EE);
    atomicAdd(&g_cnt[d], 1);
}
__global__ void k_scan1() {
    __shared__ int sh[SCAN_B];
    int tid = threadIdx.x;
    int i = blockIdx.x * SCAN_B + tid;
    int v = (i < NN) ? g_cnt[i] : 0;
    sh[tid] = v;
    __syncthreads();
    for (int off = 1; off < SCAN_B; off <<= 1) {
        int t = (tid >= off) ? sh[tid - off] : 0;
        __syncthreads();
        sh[tid] += t;
        __syncthreads();
    }
    g_incl[i] = sh[tid];
    if (tid == SCAN_B - 1) g_bsum[blockIdx.x] = sh[tid];
}
__global__ void k_scan2() {
    if (threadIdx.x == 0) {
        int s = 0;
        for (int i = 0; i < NBLK; ++i) { int t = g_bsum[i]; g_bsum[i] = s; s += t; }
    }
}
__global__ void k_scan3() {
    int i = blockIdx.x * blockDim.x + threadIdx.x;
    if (i < NN) {
        int v = g_cnt[i];
        int ex = g_incl[i] - v + g_bsum[i >> 10];
        g_rowptr[i] = ex;
        g_fill[i] = ex;
    }
    if (i == 0) g_rowptr[NN] = ET;
}
__global__ void k_fill(const int* __restrict__ ei) {
    int e = blockIdx.x * blockDim.x + threadIdx.x;
    if (e >= ET) return;
    int s, d;
    if (e < EE) { s = ei[e]; d = ei[EE + e]; }
    else        { s = e - EE; d = s; }
    int pos = atomicAdd(&g_fill[d], 1);
    g_col[pos] = s;
}

// ---------------- alpha for last layer (H=1) --------------------------------------
__global__ __launch_bounds__(256) void k_alpha1(const float* __restrict__ a_s,
                                                const float* __restrict__ a_d,
                                                float* __restrict__ as_out,
                                                float* __restrict__ ad_out) {
    int warp = (blockIdx.x * blockDim.x + threadIdx.x) >> 5;
    int lane = threadIdx.x & 31;
    if (warp >= NN) return;
    const __half2* hr = (const __half2*)(g_hhi + (size_t)warp * 64);
    const __half2* lr = (const __half2*)(g_hlo + (size_t)warp * 64);
    float2 hf = __half22float2(hr[lane]);
    float2 lf = __half22float2(lr[lane]);
    float v0 = hf.x + lf.x, v1 = hf.y + lf.y;
    float ps = v0 * a_s[2 * lane] + v1 * a_s[2 * lane + 1];
    float pd = v0 * a_d[2 * lane] + v1 * a_d[2 * lane + 1];
#pragma unroll
    for (int o = 16; o; o >>= 1) {
        ps += __shfl_xor_sync(0xffffffffu, ps, o);
        pd += __shfl_xor_sync(0xffffffffu, pd, o);
    }
    if (lane == 0) { as_out[warp] = ps; ad_out[warp] = pd; }
}

// ---------------- GAT conv: online softmax + fp16 message gather ------------------
template <int HEADS, bool RELU, bool SPLIT>
__global__ __launch_bounds__(256) void k_conv(const float* __restrict__ as_,
                                              const float* __restrict__ ad_,
                                              const float* __restrict__ bias,
                                              float* __restrict__ out,
                                              __half* __restrict__ ohi) {
    const int TC = HEADS * 64;
    const int NPL = TC / 32;
    int warp = (blockIdx.x * blockDim.x + threadIdx.x) >> 5;
    int lane = threadIdx.x & 31;
    if (warp >= NN) return;
    int beg = g_rowptr[warp], end = g_rowptr[warp + 1];

    float adh[HEADS];
#pragma unroll
    for (int hh = 0; hh < HEADS; ++hh) adh[hh] = ad_[warp * HEADS + hh];

    float mx[HEADS], sm[HEADS];
#pragma unroll
    for (int hh = 0; hh < HEADS; ++hh) { mx[hh] = -1e30f; sm[hh] = 0.f; }
    for (int i = beg + lane; i < end; i += 32) {
        int s = g_col[i];
#pragma unroll
        for (int hh = 0; hh < HEADS; ++hh) {
            float e = as_[s * HEADS + hh] + adh[hh];
            e = e > 0.f ? e : 0.2f * e;
            if (e > mx[hh]) {
                sm[hh] = sm[hh] * __expf(mx[hh] - e) + 1.f;
                mx[hh] = e;
            } else {
                sm[hh] += __expf(e - mx[hh]);
            }
        }
    }
#pragma unroll
    for (int hh = 0; hh < HEADS; ++hh) {
#pragma unroll
        for (int o = 16; o; o >>= 1) {
            float mo = __shfl_xor_sync(0xffffffffu, mx[hh], o);
            float so = __shfl_xor_sync(0xffffffffu, sm[hh], o);
            float mn = fmaxf(mx[hh], mo);
            sm[hh] = sm[hh] * __expf(mx[hh] - mn) + so * __expf(mo - mn);
            mx[hh] = mn;
        }
    }

    const int myhead = (lane * NPL) / 64;
    float mm = mx[myhead], adm = adh[myhead], inv = 1.f / sm[myhead];
    float acc[NPL] = {};
    for (int i = beg; i < end; ++i) {
        int s = g_col[i];
        float e = as_[s * HEADS + myhead] + adm;
        e = e > 0.f ? e : 0.2f * e;
        float w = __expf(e - mm) * inv;
        const __half* hp = g_hhi + (size_t)s * TC + lane * NPL;
        if constexpr (NPL == 8) {
            uint4 raw = *(const uint4*)hp;
            float2 f0 = __half22float2(*(__half2*)&raw.x);
            float2 f1 = __half22float2(*(__half2*)&raw.y);
            float2 f2 = __half22float2(*(__half2*)&raw.z);
            float2 f3 = __half22float2(*(__half2*)&raw.w);
            acc[0] += w * f0.x; acc[1] += w * f0.y; acc[2] += w * f1.x; acc[3] += w * f1.y;
            acc[4] += w * f2.x; acc[5] += w * f2.y; acc[6] += w * f3.x; acc[7] += w * f3.y;
        } else {
            uint32_t raw = *(const uint32_t*)hp;
            float2 f0 = __half22float2(*(__half2*)&raw);
            acc[0] += w * f0.x; acc[1] += w * f0.y;
        }
    }
    float dinv = 1.f / (float)(end - beg);
    float v[NPL];
#pragma unroll
    for (int j = 0; j < NPL; ++j) {
        v[j] = acc[j] * dinv + bias[lane * NPL + j];
        if (RELU) v[j] = fmaxf(v[j], 0.f);
    }
    if constexpr (SPLIT) {
        __half2 vh[NPL / 2];
#pragma unroll
        for (int j = 0; j < NPL / 2; ++j)
            vh[j] = __floats2half2_rn(v[2 * j], v[2 * j + 1]);
        *(uint4*)(ohi + (size_t)warp * TC + lane * NPL) = *(uint4*)vh;
    } else {
#pragma unroll
        for (int j = 0; j < NPL; ++j)
            out[(size_t)warp * TC + lane * NPL + j] = v[j];
    }
}

// ---------------- launch ----------------------------------------------------------
extern "C" void kernel_launch(void* const* d_in, const int* in_sizes, int n_in,
                              void* d_out, int out_size) {
    const float* x   = (const float*)d_in[0];
    const int*   ei  = (const int*)d_in[1];
    const float* W0  = (const float*)d_in[2];
    const float* a0s = (const float*)d_in[3];
    const float* a0d = (const float*)d_in[4];
    const float* b0  = (const float*)d_in[5];
    const float* W1  = (const float*)d_in[6];
    const float* a1s = (const float*)d_in[7];
    const float* a1d = (const float*)d_in[8];
    const float* b1  = (const float*)d_in[9];
    const float* W2  = (const float*)d_in[10];
    const float* a2s = (const float*)d_in[11];
    const float* a2d = (const float*)d_in[12];
    const float* b2  = (const float*)d_in[13];
    float* out = (float*)d_out;

    void* p;
    cudaGetSymbolAddress(&p, g_ahi);  __half* ahi = (__half*)p;
    cudaGetSymbolAddress(&p, g_hhi);  __half* hhi = (__half*)p;
    cudaGetSymbolAddress(&p, g_hlo);  __half* hlo = (__half*)p;
    cudaGetSymbolAddress(&p, g_w0hi); __half* w0hi = (__half*)p;
    cudaGetSymbolAddress(&p, g_w0lo); __half* w0lo = (__half*)p;
    cudaGetSymbolAddress(&p, g_w1hi); __half* w1hi = (__half*)p;
    cudaGetSymbolAddress(&p, g_w1lo); __half* w1lo = (__half*)p;
    cudaGetSymbolAddress(&p, g_w2hi); __half* w2hi = (__half*)p;
    cudaGetSymbolAddress(&p, g_w2lo); __half* w2lo = (__half*)p;
    cudaGetSymbolAddress(&p, g_as);   float* asb = (float*)p;
    cudaGetSymbolAddress(&p, g_ad);   float* adb = (float*)p;

    const int SMEM256 = 2 * (128 * 128 + 2 * 128 * 128);  // 98304
    const int SMEM64  = 2 * (128 * 128 + 2 * 64 * 128);   // 65536
    static bool attr_done = false;
    if (!attr_done) {
        cudaFuncSetAttribute(k_gemm_mma<256>, cudaFuncAttributeMaxDynamicSharedMemorySize, SMEM256);
        cudaFuncSetAttribute(k_gemm_mma<64>,  cudaFuncAttributeMaxDynamicSharedMemorySize, SMEM64);
        attr_done = true;
    }

    const int WPB = 8;
    const int NODE_BLKS = (NN + WPB - 1) / WPB;
    dim3 g256(2, (NN + 127) / 128);
    dim3 g64(1, (NN + 127) / 128);

    // launches 1-3; launch #4 (profiled) = layer-0 GEMM
    k_tofp16_x<<<(NN * 64 + 255) / 256, 256>>>(x);
    k_split_wt<256><<<(256 * 256 + 255) / 256, 256>>>(W0, w0hi, w0lo);
    k_zero_cnt<<<(NN + 255) / 256, 256>>>();
    k_gemm_mma<256><<<g256, 256, SMEM256>>>(ahi, w0hi, w0lo, hhi, nullptr, a0s, a0d);

    // CSR build
    k_count<<<(ET + 255) / 256, 256>>>(ei);
    k_scan1<<<NBLK, SCAN_B>>>();
    k_scan2<<<1, 32>>>();
    k_scan3<<<(NN + 255) / 256, 256>>>();
    k_fill<<<(ET + 255) / 256, 256>>>(ei);

    // layer 0 conv (alpha fused in GEMM epilogue)
    k_conv<4, true, true><<<NODE_BLKS, 256>>>(asb, adb, b0, nullptr, ahi);

    // layer 1
    k_split_wt<256><<<(256 * 256 + 255) / 256, 256>>>(W1, w1hi, w1lo);
    k_gemm_mma<256><<<g256, 256, SMEM256>>>(ahi, w1hi, w1lo, hhi, nullptr, a1s, a1d);
    k_conv<4, true, true><<<NODE_BLKS, 256>>>(asb, adb, b1, nullptr, ahi);

    // layer 2 (heads=1)
    k_split_wt<64><<<(256 * 64 + 255) / 256, 256>>>(W2, w2hi, w2lo);
    k_gemm_mma<64><<<g64, 256, SMEM64>>>(ahi, w2hi, w2lo, hhi, hlo, nullptr, nullptr);
    k_alpha1<<<NODE_BLKS, 256>>>(a2s, a2d, asb, adb);
    k_conv<1, false, false><<<NODE_BLKS, 256>>>(asb, adb, b2, out, nullptr);
}